// round 14
// baseline (speedup 1.0000x reference)
#include <cuda_runtime.h>
#include <cuda_fp16.h>
#include <math.h>
#include <stdint.h>

#define EMB   1024
#define DFF   4096
#define HEADS 16
#define DH    64
#define BATCH 2
#define SEQ   2048
#define TOK   (BATCH*SEQ)

typedef __half f16;

// ============================ scratch (static, no allocs) ============================
__device__ __align__(1024) f16 g_hhi  [(size_t)TOK*EMB];
__device__ __align__(1024) f16 g_hlo  [(size_t)TOK*EMB];
__device__ __align__(1024) f16 g_wqkvhi[(size_t)3*EMB*EMB];   // [3072,1024] K-major
__device__ __align__(1024) f16 g_wqkvlo[(size_t)3*EMB*EMB];
__device__ __align__(1024) f16 g_w1hi [(size_t)DFF*EMB];      // [4096,1024] single
__device__ __align__(1024) f16 g_w2hi [(size_t)EMB*DFF];      // [1024,4096] single
__device__ __align__(1024) float g_bqkv[3*EMB];
__device__ __align__(1024) f16 g_qkvhi[(size_t)TOK*3*EMB];    // [tok,3072]: q|k|v (v single)
__device__ __align__(1024) f16 g_qkvlo[(size_t)TOK*3*EMB];    // lo planes for q,k only
__device__ __align__(1024) float g_attn[(size_t)TOK*EMB];
__device__ __align__(1024) f16 g_h2hi [(size_t)TOK*EMB];      // single
__device__ __align__(1024) f16 g_ffhi [(size_t)TOK*DFF];      // single (post-gelu)

// ============================ PTX helpers ============================
__device__ __forceinline__ uint32_t smem_u32(const void* p) {
    uint32_t a;
    asm("{ .reg .u64 t; cvta.to.shared.u64 t, %1; cvt.u32.u64 %0, t; }" : "=r"(a) : "l"(p));
    return a;
}
__device__ __forceinline__ void cpasync16(uint32_t dst, const void* src) {
    asm volatile("cp.async.cg.shared.global [%0], [%1], 16;\n" :: "r"(dst), "l"(src));
}
#define CP_COMMIT()  asm volatile("cp.async.commit_group;\n" ::: "memory")
#define CP_WAIT0()   asm volatile("cp.async.wait_group 0;\n" ::: "memory")
#define CP_WAIT1()   asm volatile("cp.async.wait_group 1;\n" ::: "memory")

__device__ __forceinline__ void ldm_x4(uint32_t* r, uint32_t addr) {
    asm volatile("ldmatrix.sync.aligned.m8n8.x4.shared.b16 {%0,%1,%2,%3}, [%4];"
                 : "=r"(r[0]), "=r"(r[1]), "=r"(r[2]), "=r"(r[3]) : "r"(addr));
}
__device__ __forceinline__ void ldm_x4_t(uint32_t* r, uint32_t addr) {
    asm volatile("ldmatrix.sync.aligned.m8n8.x4.trans.shared.b16 {%0,%1,%2,%3}, [%4];"
                 : "=r"(r[0]), "=r"(r[1]), "=r"(r[2]), "=r"(r[3]) : "r"(addr));
}
__device__ __forceinline__ void mma16816(float* d, const uint32_t* a, const uint32_t* b) {
    asm volatile(
        "mma.sync.aligned.m16n8k16.row.col.f32.f16.f16.f32 "
        "{%0,%1,%2,%3}, {%4,%5,%6,%7}, {%8,%9}, {%0,%1,%2,%3};"
        : "+f"(d[0]), "+f"(d[1]), "+f"(d[2]), "+f"(d[3])
        : "r"(a[0]), "r"(a[1]), "r"(a[2]), "r"(a[3]), "r"(b[0]), "r"(b[1]));
}

#define SWZ(o) ((o) ^ (((o) >> 3) & 0x70))

__device__ __forceinline__ void split2(float v, f16& hi, f16& lo) {
    hi = __float2half_rn(v);
    lo = __float2half_rn(v - __half2float(hi));
}
__device__ __forceinline__ uint32_t pack2(f16 a, f16 b) {
    __half2 h; h.x = a; h.y = b;
    return *(uint32_t*)&h;
}

// ============================ merged QKV GEMM ============================
// C[M,3072] = h @ Wqkv^T + bqkv.
// CTAs with n0 < 2048 (q,k): 3-MMA split, split hi/lo store.
// CTAs with n0 >= 2048 (v):  1-MMA (hi only),  single hi store.
__global__ void __launch_bounds__(256)
gemmqkv_kernel(const f16* __restrict__ Ahi, const f16* __restrict__ Alo,
               const f16* __restrict__ Bhi, const f16* __restrict__ Blo,
               const float* __restrict__ bias,
               f16* __restrict__ outHi, f16* __restrict__ outLo) {
    constexpr int K = EMB, lda = EMB, ldb = EMB, ldc = 3 * EMB;
    constexpr int TN = 256;
    constexpr int ABYTES = 128 * 128;
    constexpr int BBYTES = TN * 128;
    constexpr int STAGE  = 2 * ABYTES + 2 * BBYTES;
    constexpr int WN = 64, NJ = 4;

    extern __shared__ char smem[];
    uint32_t sb = smem_u32(smem);

    int tid = threadIdx.x;
    int wid = tid >> 5, lane = tid & 31;
    int wm = wid >> 2, wn = wid & 3;
    int sub = lane >> 3, r = lane & 7;

    int m0 = blockIdx.y * 128;
    int n0 = blockIdx.x * TN;
    const bool isV = (n0 >= 2 * EMB);   // uniform per CTA

    float acc[4][NJ * 2][4];
#pragma unroll
    for (int i = 0; i < 4; i++)
#pragma unroll
        for (int j = 0; j < NJ * 2; j++)
#pragma unroll
            for (int t = 0; t < 4; t++) acc[i][j][t] = 0.f;

    const int nIter = K / 64;

    auto load_stage = [&](int it, int s) {
        int k0 = it * 64;
        uint32_t AhB = sb + s * STAGE;
        uint32_t AlB = AhB + ABYTES;
        uint32_t BhB = AlB + ABYTES;
        uint32_t BlB = BhB + BBYTES;
#pragma unroll
        for (int t = 0; t < 4; t++) {
            int idx = tid + t * 256;
            int row = idx >> 3, seg = idx & 7;
            size_t go = (size_t)(m0 + row) * lda + k0 + seg * 8;
            uint32_t so = SWZ(row * 128 + seg * 16);
            cpasync16(AhB + so, Ahi + go);
            if (!isV) cpasync16(AlB + so, Alo + go);
        }
#pragma unroll
        for (int t = 0; t < 8; t++) {
            int idx = tid + t * 256;
            int row = idx >> 3, seg = idx & 7;
            size_t go = (size_t)(n0 + row) * ldb + k0 + seg * 8;
            uint32_t so = SWZ(row * 128 + seg * 16);
            cpasync16(BhB + so, Bhi + go);
            if (!isV) cpasync16(BlB + so, Blo + go);
        }
        CP_COMMIT();
    };

    load_stage(0, 0);

    for (int it = 0; it < nIter; it++) {
        int s = it & 1;
        CP_WAIT0();
        __syncthreads();
        if (it + 1 < nIter) load_stage(it + 1, s ^ 1);

        uint32_t AhB = sb + s * STAGE;
        uint32_t AlB = AhB + ABYTES;
        uint32_t BhB = AlB + ABYTES;
        uint32_t BlB = BhB + BBYTES;

#pragma unroll
        for (int ks = 0; ks < 4; ks++) {
            uint32_t ah[4][4], al[4][4];
#pragma unroll
            for (int mi = 0; mi < 4; mi++) {
                int row = wm * 64 + mi * 16 + (sub & 1) * 8 + r;
                int kb  = ks * 32 + (sub >> 1) * 16;
                uint32_t so = SWZ(row * 128 + kb);
                ldm_x4(ah[mi], AhB + so);
                if (!isV) ldm_x4(al[mi], AlB + so);
            }
#pragma unroll
            for (int j = 0; j < NJ; j++) {
                uint32_t bh[4], bl[4];
                int nrow = wn * WN + j * 16 + (sub >> 1) * 8 + r;
                int kb   = ks * 32 + (sub & 1) * 16;
                uint32_t so = SWZ(nrow * 128 + kb);
                ldm_x4(bh, BhB + so);
                if (!isV) {
                    ldm_x4(bl, BlB + so);
#pragma unroll
                    for (int mi = 0; mi < 4; mi++)
#pragma unroll
                        for (int s2 = 0; s2 < 2; s2++) {
                            float* c = acc[mi][j * 2 + s2];
                            mma16816(c, ah[mi], &bh[s2 * 2]);
                            mma16816(c, ah[mi], &bl[s2 * 2]);
                            mma16816(c, al[mi], &bh[s2 * 2]);
                        }
                } else {
#pragma unroll
                    for (int mi = 0; mi < 4; mi++)
#pragma unroll
                        for (int s2 = 0; s2 < 2; s2++)
                            mma16816(acc[mi][j * 2 + s2], ah[mi], &bh[s2 * 2]);
                }
            }
        }
    }

    int qr = lane >> 2;
    int qc = (lane & 3) * 2;
#pragma unroll
    for (int mi = 0; mi < 4; mi++) {
#pragma unroll
        for (int jj = 0; jj < NJ * 2; jj++) {
            int cg = n0 + wn * WN + (jj >> 1) * 16 + (jj & 1) * 8 + qc;
#pragma unroll
            for (int rr = 0; rr < 2; rr++) {
                int rg = m0 + wm * 64 + mi * 16 + qr + rr * 8;
                float c0 = acc[mi][jj][rr * 2 + 0] + bias[cg];
                float c1 = acc[mi][jj][rr * 2 + 1] + bias[cg + 1];
                size_t oi = (size_t)rg * ldc + cg;
                if (!isV) {
                    f16 h0, l0, h1, l1;
                    split2(c0, h0, l0); split2(c1, h1, l1);
                    *(uint32_t*)&outHi[oi] = pack2(h0, h1);
                    *(uint32_t*)&outLo[oi] = pack2(l0, l1);
                } else {
                    *(uint32_t*)&outHi[oi] = pack2(__float2half_rn(c0), __float2half_rn(c1));
                }
            }
        }
    }
}

// ============================ 1-MMA GEMM (FFN), 3-stage ============================
// modes: 3 bias+gelu->f16; 4 bias+resid->fp32
__global__ void __launch_bounds__(256)
gemm1_kernel(const f16* __restrict__ A, int lda,
             const f16* __restrict__ B, int ldb,
             const float* __restrict__ bias,
             const float* __restrict__ resid, int ldr,
             void* outp, int ldc, int K, int mode) {
    constexpr int TN = 256;
    constexpr int ABYTES = 128 * 128;
    constexpr int BBYTES = TN * 128;
    constexpr int STAGE  = ABYTES + BBYTES;
    constexpr int WN = 64, NJ = 4;

    extern __shared__ char smem[];
    uint32_t sb = smem_u32(smem);

    int tid = threadIdx.x;
    int wid = tid >> 5, lane = tid & 31;
    int wm = wid >> 2, wn = wid & 3;
    int sub = lane >> 3, r = lane & 7;

    int m0 = blockIdx.y * 128;
    int n0 = blockIdx.x * TN;

    float acc[4][NJ * 2][4];
#pragma unroll
    for (int i = 0; i < 4; i++)
#pragma unroll
        for (int j = 0; j < NJ * 2; j++)
#pragma unroll
            for (int t = 0; t < 4; t++) acc[i][j][t] = 0.f;

    const int nIter = K / 64;

    auto load_stage = [&](int it, int s) {
        int k0 = it * 64;
        uint32_t AB = sb + s * STAGE;
        uint32_t BB = AB + ABYTES;
#pragma unroll
        for (int t = 0; t < 4; t++) {
            int idx = tid + t * 256;
            int row = idx >> 3, seg = idx & 7;
            size_t go = (size_t)(m0 + row) * lda + k0 + seg * 8;
            cpasync16(AB + SWZ(row * 128 + seg * 16), A + go);
        }
#pragma unroll
        for (int t = 0; t < 8; t++) {
            int idx = tid + t * 256;
            int row = idx >> 3, seg = idx & 7;
            size_t go = (size_t)(n0 + row) * ldb + k0 + seg * 8;
            cpasync16(BB + SWZ(row * 128 + seg * 16), B + go);
        }
        CP_COMMIT();
    };

    load_stage(0, 0);
    load_stage(1, 1);

    for (int it = 0; it < nIter; it++) {
        int s = it % 3;
        if (it + 1 < nIter) CP_WAIT1();
        else                CP_WAIT0();
        __syncthreads();
        if (it + 2 < nIter) load_stage(it + 2, (it + 2) % 3);

        uint32_t AB = sb + s * STAGE;
        uint32_t BB = AB + ABYTES;

#pragma unroll
        for (int ks = 0; ks < 4; ks++) {
            uint32_t a4[4][4];
#pragma unroll
            for (int mi = 0; mi < 4; mi++) {
                int row = wm * 64 + mi * 16 + (sub & 1) * 8 + r;
                int kb  = ks * 32 + (sub >> 1) * 16;
                ldm_x4(a4[mi], AB + SWZ(row * 128 + kb));
            }
#pragma unroll
            for (int j = 0; j < NJ; j++) {
                uint32_t b4[4];
                int nrow = wn * WN + j * 16 + (sub >> 1) * 8 + r;
                int kb   = ks * 32 + (sub & 1) * 16;
                ldm_x4(b4, BB + SWZ(nrow * 128 + kb));
#pragma unroll
                for (int mi = 0; mi < 4; mi++)
#pragma unroll
                    for (int s2 = 0; s2 < 2; s2++)
                        mma16816(acc[mi][j * 2 + s2], a4[mi], &b4[s2 * 2]);
            }
        }
    }

    int qr = lane >> 2;
    int qc = (lane & 3) * 2;
#pragma unroll
    for (int mi = 0; mi < 4; mi++) {
#pragma unroll
        for (int jj = 0; jj < NJ * 2; jj++) {
            int cg = n0 + wn * WN + (jj >> 1) * 16 + (jj & 1) * 8 + qc;
#pragma unroll
            for (int rr = 0; rr < 2; rr++) {
                int rg = m0 + wm * 64 + mi * 16 + qr + rr * 8;
                float c0 = acc[mi][jj][rr * 2 + 0] + bias[cg];
                float c1 = acc[mi][jj][rr * 2 + 1] + bias[cg + 1];
                if (mode == 4) {
                    c0 += resid[(size_t)rg * ldr + cg];
                    c1 += resid[(size_t)rg * ldr + cg + 1];
                    float* o = (float*)outp;
                    *(float2*)&o[(size_t)rg * ldc + cg] = make_float2(c0, c1);
                } else {
                    c0 = 0.5f * c0 * (1.0f + erff(c0 * 0.70710678118654752f));
                    c1 = 0.5f * c1 * (1.0f + erff(c1 * 0.70710678118654752f));
                    f16* o = (f16*)outp;
                    *(uint32_t*)&o[(size_t)rg * ldc + cg] =
                        pack2(__float2half_rn(c0), __float2half_rn(c1));
                }
            }
        }
    }
}

// ============================ fused flash attention, 3-stage KV ============================
__global__ void __launch_bounds__(256)
fattn_kernel(const f16* __restrict__ qkvhi, const f16* __restrict__ qkvlo,
             const float* __restrict__ x, float* __restrict__ attn) {
    constexpr int BUF = 128 * 128;
    constexpr int LD  = 3 * EMB;
    constexpr int NJT = SEQ / 128;
    extern __shared__ char smem[];
    uint32_t sb = smem_u32(smem);
    const uint32_t QHb = sb, QLb = sb + BUF;
    const uint32_t ST0 = sb + 2 * BUF;

    int tid = threadIdx.x, wid = tid >> 5, lane = tid & 31;
    int sub = lane >> 3, r = lane & 7;
    int z = blockIdx.y, zb = z >> 4, zh = z & 15;
    int m0 = blockIdx.x * 128;

    const size_t rowbase = (size_t)zb * SEQ;
    const int qcol = zh * DH, kcol = EMB + zh * DH, vcol = 2 * EMB + zh * DH;

#pragma unroll
    for (int t = 0; t < 4; t++) {
        int idx = tid + t * 256;
        int row = idx >> 3, seg = idx & 7;
        size_t go = (rowbase + m0 + row) * LD + qcol + seg * 8;
        uint32_t so = SWZ(row * 128 + seg * 16);
        cpasync16(QHb + so, qkvhi + go);
        cpasync16(QLb + so, qkvlo + go);
    }
    CP_COMMIT();
    auto load_kv = [&](int j, int s) {
        uint32_t base = ST0 + s * 3 * BUF;
        int k0 = j * 128;
#pragma unroll
        for (int t = 0; t < 4; t++) {
            int idx = tid + t * 256;
            int row = idx >> 3, seg = idx & 7;
            size_t gk = (rowbase + k0 + row) * LD + kcol + seg * 8;
            size_t gv = (rowbase + k0 + row) * LD + vcol + seg * 8;
            uint32_t so = SWZ(row * 128 + seg * 16);
            cpasync16(base + 0 * BUF + so, qkvhi + gk);
            cpasync16(base + 1 * BUF + so, qkvlo + gk);
            cpasync16(base + 2 * BUF + so, qkvhi + gv);
        }
        CP_COMMIT();
    };
    load_kv(0, 0);
    load_kv(1, 1);

    uint32_t qh[4][4], ql[4][4];
    float mr0 = -1e30f, mr1 = -1e30f, lr0 = 0.f, lr1 = 0.f;
    float oacc[8][4];
#pragma unroll
    for (int d = 0; d < 8; d++)
#pragma unroll
        for (int t = 0; t < 4; t++) oacc[d][t] = 0.f;

    for (int j = 0; j < NJT; j++) {
        int s = j % 3;
        if (j + 1 < NJT) CP_WAIT1();
        else             CP_WAIT0();
        __syncthreads();
        if (j == 0) {
#pragma unroll
            for (int ks = 0; ks < 4; ks++) {
                int row = wid * 16 + (sub & 1) * 8 + r;
                int kb  = ks * 32 + (sub >> 1) * 16;
                uint32_t so = SWZ(row * 128 + kb);
                ldm_x4(qh[ks], QHb + so);
                ldm_x4(ql[ks], QLb + so);
            }
        }
        if (j + 2 < NJT) load_kv(j + 2, (j + 2) % 3);

        uint32_t KHb = ST0 + s * 3 * BUF;
        uint32_t KLb = KHb + BUF, VHb = KLb + BUF;

        float sacc[16][4];
#pragma unroll
        for (int g = 0; g < 16; g++)
#pragma unroll
            for (int t = 0; t < 4; t++) sacc[g][t] = 0.f;

#pragma unroll
        for (int ks = 0; ks < 4; ks++) {
#pragma unroll
            for (int g = 0; g < 8; g++) {
                uint32_t bh[4], bl[4];
                int nrow = g * 16 + (sub >> 1) * 8 + r;
                int kb   = ks * 32 + (sub & 1) * 16;
                uint32_t so = SWZ(nrow * 128 + kb);
                ldm_x4(bh, KHb + so);
                ldm_x4(bl, KLb + so);
#pragma unroll
                for (int s2 = 0; s2 < 2; s2++) {
                    float* c = sacc[g * 2 + s2];
                    mma16816(c, qh[ks], &bh[s2 * 2]);
                    mma16816(c, qh[ks], &bl[s2 * 2]);
                    mma16816(c, ql[ks], &bh[s2 * 2]);
                }
            }
        }

        float mx0 = -1e30f, mx1 = -1e30f;
#pragma unroll
        for (int g = 0; g < 16; g++) {
            mx0 = fmaxf(mx0, fmaxf(sacc[g][0], sacc[g][1]));
            mx1 = fmaxf(mx1, fmaxf(sacc[g][2], sacc[g][3]));
        }
        mx0 = fmaxf(mx0, __shfl_xor_sync(0xFFFFFFFFu, mx0, 1));
        mx0 = fmaxf(mx0, __shfl_xor_sync(0xFFFFFFFFu, mx0, 2));
        mx1 = fmaxf(mx1, __shfl_xor_sync(0xFFFFFFFFu, mx1, 1));
        mx1 = fmaxf(mx1, __shfl_xor_sync(0xFFFFFFFFu, mx1, 2));

        float mn0 = fmaxf(mr0, mx0), mn1 = fmaxf(mr1, mx1);
        float a0 = __expf(mr0 - mn0), a1 = __expf(mr1 - mn1);
        mr0 = mn0; mr1 = mn1;

        float sum0 = 0.f, sum1 = 0.f;
#pragma unroll
        for (int g = 0; g < 16; g++) {
            sacc[g][0] = __expf(sacc[g][0] - mn0);
            sacc[g][1] = __expf(sacc[g][1] - mn0);
            sacc[g][2] = __expf(sacc[g][2] - mn1);
            sacc[g][3] = __expf(sacc[g][3] - mn1);
            sum0 += sacc[g][0] + sacc[g][1];
            sum1 += sacc[g][2] + sacc[g][3];
        }
        sum0 += __shfl_xor_sync(0xFFFFFFFFu, sum0, 1);
        sum0 += __shfl_xor_sync(0xFFFFFFFFu, sum0, 2);
        sum1 += __shfl_xor_sync(0xFFFFFFFFu, sum1, 1);
        sum1 += __shfl_xor_sync(0xFFFFFFFFu, sum1, 2);
        lr0 = lr0 * a0 + sum0;
        lr1 = lr1 * a1 + sum1;
#pragma unroll
        for (int d = 0; d < 8; d++) {
            oacc[d][0] *= a0; oacc[d][1] *= a0;
            oacc[d][2] *= a1; oacc[d][3] *= a1;
        }

#pragma unroll
        for (int t = 0; t < 8; t++) {
            uint32_t pah[4];
            pah[0] = pack2(__float2half_rn(sacc[2 * t][0]),     __float2half_rn(sacc[2 * t][1]));
            pah[1] = pack2(__float2half_rn(sacc[2 * t][2]),     __float2half_rn(sacc[2 * t][3]));
            pah[2] = pack2(__float2half_rn(sacc[2 * t + 1][0]), __float2half_rn(sacc[2 * t + 1][1]));
            pah[3] = pack2(__float2half_rn(sacc[2 * t + 1][2]), __float2half_rn(sacc[2 * t + 1][3]));
#pragma unroll
            for (int gd = 0; gd < 4; gd++) {
                uint32_t vh4[4];
                int krow = t * 16 + (sub & 1) * 8 + r;
                int nb   = gd * 32 + (sub >> 1) * 16;
                ldm_x4_t(vh4, VHb + SWZ(krow * 128 + nb));
#pragma unroll
                for (int s2 = 0; s2 < 2; s2++)
                    mma16816(oacc[gd * 2 + s2], pah, &vh4[s2 * 2]);
            }
        }
    }

    float li0 = 1.f / lr0, li1 = 1.f / lr1;
    int qr = lane >> 2, qc = (lane & 3) * 2;
    size_t row0 = rowbase + m0 + wid * 16 + qr;
    size_t row1 = row0 + 8;
#pragma unroll
    for (int gd = 0; gd < 8; gd++) {
        int cg = zh * DH + gd * 8 + qc;
        float2 xr0 = *(const float2*)&x[row0 * EMB + cg];
        float2 xr1 = *(const float2*)&x[row1 * EMB + cg];
        float2 o0 = make_float2(oacc[gd][0] * li0 + xr0.x, oacc[gd][1] * li0 + xr0.y);
        float2 o1 = make_float2(oacc[gd][2] * li1 + xr1.x, oacc[gd][3] * li1 + xr1.y);
        *(float2*)&attn[row0 * EMB + cg] = o0;
        *(float2*)&attn[row1 * EMB + cg] = o1;
    }
}

// ============================ LayerNorm (device helper) ============================
__device__ __forceinline__ void ln_row(const float* __restrict__ xr,
                                       const float* __restrict__ gamma,
                                       const float* __restrict__ beta,
                                       f16* __restrict__ ohi, f16* __restrict__ olo,
                                       int tid) {
    float v[4];
    float s = 0.f, s2 = 0.f;
#pragma unroll
    for (int i = 0; i < 4; i++) {
        float t = xr[tid + i * 256];
        v[i] = t; s += t; s2 += t * t;
    }
#pragma unroll
    for (int o = 16; o > 0; o >>= 1) {
        s  += __shfl_down_sync(0xFFFFFFFFu, s,  o);
        s2 += __shfl_down_sync(0xFFFFFFFFu, s2, o);
    }
    __shared__ float rs[8], rs2[8], mu_s, rstd_s;
    int wid = tid >> 5, lane = tid & 31;
    if (lane == 0) { rs[wid] = s; rs2[wid] = s2; }
    __syncthreads();
    if (wid == 0) {
        float a  = (lane < 8) ? rs[lane]  : 0.f;
        float a2 = (lane < 8) ? rs2[lane] : 0.f;
#pragma unroll
        for (int o = 4; o > 0; o >>= 1) {
            a  += __shfl_down_sync(0xFFFFFFFFu, a,  o);
            a2 += __shfl_down_sync(0xFFFFFFFFu, a2, o);
        }
        if (lane == 0) {
            float mu = a * (1.0f / EMB);
            mu_s = mu;
            rstd_s = rsqrtf(a2 * (1.0f / EMB) - mu * mu + 1e-6f);
        }
    }
    __syncthreads();
    float mu = mu_s, rstd = rstd_s;
#pragma unroll
    for (int i = 0; i < 4; i++) {
        int c = tid + i * 256;
        float val = (v[i] - mu) * rstd * gamma[c] + beta[c];
        f16 h_, l_; split2(val, h_, l_);
        ohi[c] = h_;
        if (olo) olo[c] = l_;
    }
}

__global__ void ln_split_kernel(const float* __restrict__ x,
                                const float* __restrict__ gamma,
                                const float* __restrict__ beta,
                                f16* __restrict__ ohi, f16* __restrict__ olo) {
    int row = blockIdx.x;
    ln_row(x + (size_t)row * EMB, gamma, beta,
           ohi + (size_t)row * EMB, olo ? olo + (size_t)row * EMB : nullptr,
           threadIdx.x);
}

// ============================ combined weight prep + LN1 ============================
// bid < 11264: weight transpose+split (+bias pack at bid 0).
// bid >= 11264: LN1 on row (bid - 11264).
__global__ void prep_kernel(const float* __restrict__ Wq, const float* __restrict__ Wk,
                            const float* __restrict__ Wv, const float* __restrict__ W1,
                            const float* __restrict__ W2,
                            const float* __restrict__ bq, const float* __restrict__ bk,
                            const float* __restrict__ bv,
                            f16* __restrict__ wqkvhi, f16* __restrict__ wqkvlo,
                            f16* __restrict__ w1hi, f16* __restrict__ w2hi,
                            float* __restrict__ bqkv,
                            const float* __restrict__ x,
                            const float* __restrict__ g1, const float* __restrict__ be1,
                            f16* __restrict__ hhi, f16* __restrict__ hlo) {
    int bid = blockIdx.x;
    int tx = threadIdx.x, ty = threadIdx.y;
    int tid = ty * 32 + tx;

    if (bid >= 11264) {                 // --- LN1 rows ---
        int row = bid - 11264;
        ln_row(x + (size_t)row * EMB, g1, be1,
               hhi + (size_t)row * EMB, hlo + (size_t)row * EMB, tid);
        return;
    }

    if (bid == 0) {
        for (int i = tid; i < EMB; i += 256) {
            bqkv[i]           = bq[i];
            bqkv[EMB + i]     = bk[i];
            bqkv[2 * EMB + i] = bv[i];
        }
    }

    const float* W; f16 *Thi, *Tlo; int K, N, nx, ky;
    if (bid < 3072) {
        int w = bid >> 10, t = bid & 1023;
        W = (w == 0) ? Wq : (w == 1) ? Wk : Wv;
        Thi = wqkvhi + (size_t)w * EMB * EMB;
        Tlo = wqkvlo + (size_t)w * EMB * EMB;
        K = EMB; N = EMB; nx = t & 31; ky = t >> 5;
    } else if (bid < 7168) {
        int t = bid - 3072;
        W = W1; Thi = w1hi; Tlo = nullptr;
        K = EMB; N = DFF; nx = t & 127; ky = t >> 7;
    } else {
        int t = bid - 7168;
        W = W2; Thi = w2hi; Tlo = nullptr;
        K = DFF; N = EMB; nx = t & 31; ky = t >> 5;
    }
    int n0 = nx * 32, k0 = ky * 32;

    __shared__ float tbuf[32][33];
#pragma unroll
    for (int i = ty; i < 32; i += 8)
        tbuf[i][tx] = W[(size_t)(k0 + i) * N + n0 + tx];
    __syncthreads();
#pragma unroll
    for (int i = ty; i < 32; i += 8) {
        float v = tbuf[tx][i];
        f16 h_, l_; split2(v, h_, l_);
        size_t oi = (size_t)(n0 + i) * K + k0 + tx;
        Thi[oi] = h_;
        if (Tlo) Tlo[oi] = l_;
    }
}

// ============================ launch ============================
extern "C" void kernel_launch(void* const* d_in, const int* in_sizes, int n_in,
                              void* d_out, int out_size) {
    const float* x   = (const float*)d_in[0];
    const float* Wq  = (const float*)d_in[1];
    const float* bq  = (const float*)d_in[2];
    const float* Wk  = (const float*)d_in[3];
    const float* bk  = (const float*)d_in[4];
    const float* Wv  = (const float*)d_in[5];
    const float* bv  = (const float*)d_in[6];
    const float* g1  = (const float*)d_in[7];
    const float* be1 = (const float*)d_in[8];
    const float* g2  = (const float*)d_in[9];
    const float* be2 = (const float*)d_in[10];
    const float* W1  = (const float*)d_in[11];
    const float* b1  = (const float*)d_in[12];
    const float* W2  = (const float*)d_in[13];
    const float* b2  = (const float*)d_in[14];
    float* out = (float*)d_out;

    f16 *hhi, *hlo, *wqkvhi, *wqkvlo, *w1hi, *w2hi;
    f16 *qkvhi, *qkvlo, *h2hi, *ffhi;
    float *attn, *bqkv;
    cudaGetSymbolAddress((void**)&hhi,    g_hhi);    cudaGetSymbolAddress((void**)&hlo,    g_hlo);
    cudaGetSymbolAddress((void**)&wqkvhi, g_wqkvhi); cudaGetSymbolAddress((void**)&wqkvlo, g_wqkvlo);
    cudaGetSymbolAddress((void**)&w1hi,   g_w1hi);
    cudaGetSymbolAddress((void**)&w2hi,   g_w2hi);
    cudaGetSymbolAddress((void**)&qkvhi,  g_qkvhi);  cudaGetSymbolAddress((void**)&qkvlo,  g_qkvlo);
    cudaGetSymbolAddress((void**)&attn,   g_attn);
    cudaGetSymbolAddress((void**)&h2hi,   g_h2hi);
    cudaGetSymbolAddress((void**)&ffhi,   g_ffhi);
    cudaGetSymbolAddress((void**)&bqkv,   g_bqkv);

    const int SMEM_G3 = 2 * (2 * 128 * 128 + 2 * 256 * 128);   // 196608 (2-stage)
    const int SMEM_G1 = 3 * (128 * 128 + 256 * 128);            // 147456 (3-stage)
    const int SMEM_F  = (2 + 9) * 16384;                        // 180224
    cudaFuncSetAttribute(gemmqkv_kernel, cudaFuncAttributeMaxDynamicSharedMemorySize, SMEM_G3);
    cudaFuncSetAttribute(gemm1_kernel,   cudaFuncAttributeMaxDynamicSharedMemorySize, SMEM_G1);
    cudaFuncSetAttribute(fattn_kernel,   cudaFuncAttributeMaxDynamicSharedMemorySize, SMEM_F);

    // 0) weight prep + LN1 (one launch)
    prep_kernel<<<11264 + TOK, dim3(32, 8)>>>(Wq, Wk, Wv, W1, W2, bq, bk, bv,
                                              wqkvhi, wqkvlo, w1hi, w2hi, bqkv,
                                              x, g1, be1, hhi, hlo);

    // 1) merged QKV projection -> packed qkv
    {
        dim3 grid(3 * EMB / 256, TOK / 128);
        gemmqkv_kernel<<<grid, 256, SMEM_G3>>>(hhi, hlo, wqkvhi, wqkvlo, bqkv, qkvhi, qkvlo);
    }

    // 2) fused attention (+ residual x) -> attn
    {
        dim3 grid(SEQ / 128, BATCH * HEADS);
        fattn_kernel<<<grid, 256, SMEM_F>>>(qkvhi, qkvlo, x, attn);
    }

    // 3) LN2 -> single f16
    ln_split_kernel<<<TOK, 256>>>(attn, g2, be2, h2hi, nullptr);

    // 4) FFN1 (1-MMA, bias+gelu) -> f16
    {
        dim3 grid(DFF / 256, TOK / 128);
        gemm1_kernel<<<grid, 256, SMEM_G1>>>(h2hi, EMB, w1hi, EMB,
                                             b1, nullptr, 0, ffhi, DFF, EMB, 3);
    }

    // 5) FFN2 (1-MMA, bias + attn residual) -> d_out
    {
        dim3 grid(EMB / 256, TOK / 128);
        gemm1_kernel<<<grid, 256, SMEM_G1>>>(ffhi, DFF, w2hi, DFF,
                                             b2, attn, EMB, out, EMB, DFF, 4);
    }
}

// round 15
// speedup vs baseline: 1.0055x; 1.0055x over previous
#include <cuda_runtime.h>
#include <cuda_fp16.h>
#include <math.h>
#include <stdint.h>

#define EMB   1024
#define DFF   4096
#define HEADS 16
#define DH    64
#define BATCH 2
#define SEQ   2048
#define TOK   (BATCH*SEQ)

typedef __half f16;

// ============================ scratch (static, no allocs) ============================
__device__ __align__(1024) f16 g_hhi  [(size_t)TOK*EMB];
__device__ __align__(1024) f16 g_hlo  [(size_t)TOK*EMB];
__device__ __align__(1024) f16 g_wqkvhi[(size_t)3*EMB*EMB];   // [3072,1024] K-major
__device__ __align__(1024) f16 g_wqkvlo[(size_t)3*EMB*EMB];
__device__ __align__(1024) f16 g_w1hi [(size_t)DFF*EMB];      // [4096,1024] single
__device__ __align__(1024) f16 g_w2hi [(size_t)EMB*DFF];      // [1024,4096] single
__device__ __align__(1024) float g_bqkv[3*EMB];
__device__ __align__(1024) f16 g_qkvhi[(size_t)TOK*3*EMB];    // [tok,3072]: q|k|v (v single)
__device__ __align__(1024) f16 g_qkvlo[(size_t)TOK*3*EMB];    // lo planes for q,k only
__device__ __align__(1024) float g_attn[(size_t)TOK*EMB];
__device__ __align__(1024) f16 g_h2hi [(size_t)TOK*EMB];      // single
__device__ __align__(1024) f16 g_ffhi [(size_t)TOK*DFF];      // single (post-gelu)

// ============================ PTX helpers ============================
__device__ __forceinline__ uint32_t smem_u32(const void* p) {
    uint32_t a;
    asm("{ .reg .u64 t; cvta.to.shared.u64 t, %1; cvt.u32.u64 %0, t; }" : "=r"(a) : "l"(p));
    return a;
}
__device__ __forceinline__ void cpasync16(uint32_t dst, const void* src) {
    asm volatile("cp.async.cg.shared.global [%0], [%1], 16;\n" :: "r"(dst), "l"(src));
}
#define CP_COMMIT()  asm volatile("cp.async.commit_group;\n" ::: "memory")
#define CP_WAIT0()   asm volatile("cp.async.wait_group 0;\n" ::: "memory")
#define CP_WAIT1()   asm volatile("cp.async.wait_group 1;\n" ::: "memory")

__device__ __forceinline__ void ldm_x4(uint32_t* r, uint32_t addr) {
    asm volatile("ldmatrix.sync.aligned.m8n8.x4.shared.b16 {%0,%1,%2,%3}, [%4];"
                 : "=r"(r[0]), "=r"(r[1]), "=r"(r[2]), "=r"(r[3]) : "r"(addr));
}
__device__ __forceinline__ void ldm_x4_t(uint32_t* r, uint32_t addr) {
    asm volatile("ldmatrix.sync.aligned.m8n8.x4.trans.shared.b16 {%0,%1,%2,%3}, [%4];"
                 : "=r"(r[0]), "=r"(r[1]), "=r"(r[2]), "=r"(r[3]) : "r"(addr));
}
__device__ __forceinline__ void mma16816(float* d, const uint32_t* a, const uint32_t* b) {
    asm volatile(
        "mma.sync.aligned.m16n8k16.row.col.f32.f16.f16.f32 "
        "{%0,%1,%2,%3}, {%4,%5,%6,%7}, {%8,%9}, {%0,%1,%2,%3};"
        : "+f"(d[0]), "+f"(d[1]), "+f"(d[2]), "+f"(d[3])
        : "r"(a[0]), "r"(a[1]), "r"(a[2]), "r"(a[3]), "r"(b[0]), "r"(b[1]));
}

#define SWZ(o) ((o) ^ (((o) >> 3) & 0x70))

__device__ __forceinline__ void split2(float v, f16& hi, f16& lo) {
    hi = __float2half_rn(v);
    lo = __float2half_rn(v - __half2float(hi));
}
__device__ __forceinline__ uint32_t pack2(f16 a, f16 b) {
    __half2 h; h.x = a; h.y = b;
    return *(uint32_t*)&h;
}

// ============================ 3-MMA split GEMM (q,k projection) ============================
__global__ void __launch_bounds__(256)
gemm3_kernel(const f16* __restrict__ Ahi, const f16* __restrict__ Alo,
             const f16* __restrict__ Bhi, const f16* __restrict__ Blo,
             const float* __restrict__ bias,
             f16* __restrict__ outHi, f16* __restrict__ outLo) {
    constexpr int K = EMB, lda = EMB, ldb = EMB, ldc = 3 * EMB;
    constexpr int TN = 256;
    constexpr int ABYTES = 128 * 128;
    constexpr int BBYTES = TN * 128;
    constexpr int STAGE  = 2 * ABYTES + 2 * BBYTES;
    constexpr int WN = 64, NJ = 4;

    extern __shared__ char smem[];
    uint32_t sb = smem_u32(smem);

    int tid = threadIdx.x;
    int wid = tid >> 5, lane = tid & 31;
    int wm = wid >> 2, wn = wid & 3;
    int sub = lane >> 3, r = lane & 7;

    int m0 = blockIdx.y * 128;
    int n0 = blockIdx.x * TN;

    float acc[4][NJ * 2][4];
#pragma unroll
    for (int i = 0; i < 4; i++)
#pragma unroll
        for (int j = 0; j < NJ * 2; j++)
#pragma unroll
            for (int t = 0; t < 4; t++) acc[i][j][t] = 0.f;

    const int nIter = K / 64;

    auto load_stage = [&](int it, int s) {
        int k0 = it * 64;
        uint32_t AhB = sb + s * STAGE;
        uint32_t AlB = AhB + ABYTES;
        uint32_t BhB = AlB + ABYTES;
        uint32_t BlB = BhB + BBYTES;
#pragma unroll
        for (int t = 0; t < 4; t++) {
            int idx = tid + t * 256;
            int row = idx >> 3, seg = idx & 7;
            size_t go = (size_t)(m0 + row) * lda + k0 + seg * 8;
            uint32_t so = SWZ(row * 128 + seg * 16);
            cpasync16(AhB + so, Ahi + go);
            cpasync16(AlB + so, Alo + go);
        }
#pragma unroll
        for (int t = 0; t < 8; t++) {
            int idx = tid + t * 256;
            int row = idx >> 3, seg = idx & 7;
            size_t go = (size_t)(n0 + row) * ldb + k0 + seg * 8;
            uint32_t so = SWZ(row * 128 + seg * 16);
            cpasync16(BhB + so, Bhi + go);
            cpasync16(BlB + so, Blo + go);
        }
        CP_COMMIT();
    };

    load_stage(0, 0);

    for (int it = 0; it < nIter; it++) {
        int s = it & 1;
        CP_WAIT0();
        __syncthreads();
        if (it + 1 < nIter) load_stage(it + 1, s ^ 1);

        uint32_t AhB = sb + s * STAGE;
        uint32_t AlB = AhB + ABYTES;
        uint32_t BhB = AlB + ABYTES;
        uint32_t BlB = BhB + BBYTES;

#pragma unroll
        for (int ks = 0; ks < 4; ks++) {
            uint32_t ah[4][4], al[4][4];
#pragma unroll
            for (int mi = 0; mi < 4; mi++) {
                int row = wm * 64 + mi * 16 + (sub & 1) * 8 + r;
                int kb  = ks * 32 + (sub >> 1) * 16;
                uint32_t so = SWZ(row * 128 + kb);
                ldm_x4(ah[mi], AhB + so);
                ldm_x4(al[mi], AlB + so);
            }
#pragma unroll
            for (int j = 0; j < NJ; j++) {
                uint32_t bh[4], bl[4];
                int nrow = wn * WN + j * 16 + (sub >> 1) * 8 + r;
                int kb   = ks * 32 + (sub & 1) * 16;
                uint32_t so = SWZ(nrow * 128 + kb);
                ldm_x4(bh, BhB + so);
                ldm_x4(bl, BlB + so);
#pragma unroll
                for (int mi = 0; mi < 4; mi++)
#pragma unroll
                    for (int s2 = 0; s2 < 2; s2++) {
                        float* c = acc[mi][j * 2 + s2];
                        mma16816(c, ah[mi], &bh[s2 * 2]);
                        mma16816(c, ah[mi], &bl[s2 * 2]);
                        mma16816(c, al[mi], &bh[s2 * 2]);
                    }
            }
        }
    }

    int qr = lane >> 2;
    int qc = (lane & 3) * 2;
#pragma unroll
    for (int mi = 0; mi < 4; mi++) {
#pragma unroll
        for (int jj = 0; jj < NJ * 2; jj++) {
            int cg = n0 + wn * WN + (jj >> 1) * 16 + (jj & 1) * 8 + qc;
#pragma unroll
            for (int rr = 0; rr < 2; rr++) {
                int rg = m0 + wm * 64 + mi * 16 + qr + rr * 8;
                float c0 = acc[mi][jj][rr * 2 + 0] + bias[cg];
                float c1 = acc[mi][jj][rr * 2 + 1] + bias[cg + 1];
                size_t oi = (size_t)rg * ldc + cg;
                f16 h0, l0, h1, l1;
                split2(c0, h0, l0); split2(c1, h1, l1);
                *(uint32_t*)&outHi[oi] = pack2(h0, h1);
                *(uint32_t*)&outLo[oi] = pack2(l0, l1);
            }
        }
    }
}

// ============================ 1-MMA GEMM (FFN + v projection), 3-stage ============================
__global__ void __launch_bounds__(256)
gemm1_kernel(const f16* __restrict__ A, int lda,
             const f16* __restrict__ B, int ldb,
             const float* __restrict__ bias,
             const float* __restrict__ resid, int ldr,
             void* outp, int ldc, int K, int mode) {
    constexpr int TN = 256;
    constexpr int ABYTES = 128 * 128;
    constexpr int BBYTES = TN * 128;
    constexpr int STAGE  = ABYTES + BBYTES;
    constexpr int WN = 64, NJ = 4;

    extern __shared__ char smem[];
    uint32_t sb = smem_u32(smem);

    int tid = threadIdx.x;
    int wid = tid >> 5, lane = tid & 31;
    int wm = wid >> 2, wn = wid & 3;
    int sub = lane >> 3, r = lane & 7;

    int m0 = blockIdx.y * 128;
    int n0 = blockIdx.x * TN;

    float acc[4][NJ * 2][4];
#pragma unroll
    for (int i = 0; i < 4; i++)
#pragma unroll
        for (int j = 0; j < NJ * 2; j++)
#pragma unroll
            for (int t = 0; t < 4; t++) acc[i][j][t] = 0.f;

    const int nIter = K / 64;

    auto load_stage = [&](int it, int s) {
        int k0 = it * 64;
        uint32_t AB = sb + s * STAGE;
        uint32_t BB = AB + ABYTES;
#pragma unroll
        for (int t = 0; t < 4; t++) {
            int idx = tid + t * 256;
            int row = idx >> 3, seg = idx & 7;
            size_t go = (size_t)(m0 + row) * lda + k0 + seg * 8;
            cpasync16(AB + SWZ(row * 128 + seg * 16), A + go);
        }
#pragma unroll
        for (int t = 0; t < 8; t++) {
            int idx = tid + t * 256;
            int row = idx >> 3, seg = idx & 7;
            size_t go = (size_t)(n0 + row) * ldb + k0 + seg * 8;
            cpasync16(BB + SWZ(row * 128 + seg * 16), B + go);
        }
        CP_COMMIT();
    };

    load_stage(0, 0);
    load_stage(1, 1);

    for (int it = 0; it < nIter; it++) {
        int s = it % 3;
        if (it + 1 < nIter) CP_WAIT1();
        else                CP_WAIT0();
        __syncthreads();
        if (it + 2 < nIter) load_stage(it + 2, (it + 2) % 3);

        uint32_t AB = sb + s * STAGE;
        uint32_t BB = AB + ABYTES;

#pragma unroll
        for (int ks = 0; ks < 4; ks++) {
            uint32_t a4[4][4];
#pragma unroll
            for (int mi = 0; mi < 4; mi++) {
                int row = wm * 64 + mi * 16 + (sub & 1) * 8 + r;
                int kb  = ks * 32 + (sub >> 1) * 16;
                ldm_x4(a4[mi], AB + SWZ(row * 128 + kb));
            }
#pragma unroll
            for (int j = 0; j < NJ; j++) {
                uint32_t b4[4];
                int nrow = wn * WN + j * 16 + (sub >> 1) * 8 + r;
                int kb   = ks * 32 + (sub & 1) * 16;
                ldm_x4(b4, BB + SWZ(nrow * 128 + kb));
#pragma unroll
                for (int mi = 0; mi < 4; mi++)
#pragma unroll
                    for (int s2 = 0; s2 < 2; s2++)
                        mma16816(acc[mi][j * 2 + s2], a4[mi], &b4[s2 * 2]);
            }
        }
    }

    int qr = lane >> 2;
    int qc = (lane & 3) * 2;
#pragma unroll
    for (int mi = 0; mi < 4; mi++) {
#pragma unroll
        for (int jj = 0; jj < NJ * 2; jj++) {
            int cg = n0 + wn * WN + (jj >> 1) * 16 + (jj & 1) * 8 + qc;
#pragma unroll
            for (int rr = 0; rr < 2; rr++) {
                int rg = m0 + wm * 64 + mi * 16 + qr + rr * 8;
                float c0 = acc[mi][jj][rr * 2 + 0] + bias[cg];
                float c1 = acc[mi][jj][rr * 2 + 1] + bias[cg + 1];
                if (mode == 4) {
                    c0 += resid[(size_t)rg * ldr + cg];
                    c1 += resid[(size_t)rg * ldr + cg + 1];
                    float* o = (float*)outp;
                    *(float2*)&o[(size_t)rg * ldc + cg] = make_float2(c0, c1);
                } else {
                    if (mode == 3) {
                        c0 = 0.5f * c0 * (1.0f + erff(c0 * 0.70710678118654752f));
                        c1 = 0.5f * c1 * (1.0f + erff(c1 * 0.70710678118654752f));
                    }
                    f16* o = (f16*)outp;
                    *(uint32_t*)&o[(size_t)rg * ldc + cg] =
                        pack2(__float2half_rn(c0), __float2half_rn(c1));
                }
            }
        }
    }
}

// ============================ fused flash attention, 3-stage KV ============================
// Softmax exp (MUFU) interleaved with PV MMAs per 16-row group for pipe overlap.
__global__ void __launch_bounds__(256)
fattn_kernel(const f16* __restrict__ qkvhi, const f16* __restrict__ qkvlo,
             const float* __restrict__ x, float* __restrict__ attn) {
    constexpr int BUF = 128 * 128;
    constexpr int LD  = 3 * EMB;
    constexpr int NJT = SEQ / 128;
    extern __shared__ char smem[];
    uint32_t sb = smem_u32(smem);
    const uint32_t QHb = sb, QLb = sb + BUF;
    const uint32_t ST0 = sb + 2 * BUF;

    int tid = threadIdx.x, wid = tid >> 5, lane = tid & 31;
    int sub = lane >> 3, r = lane & 7;
    int z = blockIdx.y, zb = z >> 4, zh = z & 15;
    int m0 = blockIdx.x * 128;

    const size_t rowbase = (size_t)zb * SEQ;
    const int qcol = zh * DH, kcol = EMB + zh * DH, vcol = 2 * EMB + zh * DH;

#pragma unroll
    for (int t = 0; t < 4; t++) {
        int idx = tid + t * 256;
        int row = idx >> 3, seg = idx & 7;
        size_t go = (rowbase + m0 + row) * LD + qcol + seg * 8;
        uint32_t so = SWZ(row * 128 + seg * 16);
        cpasync16(QHb + so, qkvhi + go);
        cpasync16(QLb + so, qkvlo + go);
    }
    CP_COMMIT();
    auto load_kv = [&](int j, int s) {
        uint32_t base = ST0 + s * 3 * BUF;
        int k0 = j * 128;
#pragma unroll
        for (int t = 0; t < 4; t++) {
            int idx = tid + t * 256;
            int row = idx >> 3, seg = idx & 7;
            size_t gk = (rowbase + k0 + row) * LD + kcol + seg * 8;
            size_t gv = (rowbase + k0 + row) * LD + vcol + seg * 8;
            uint32_t so = SWZ(row * 128 + seg * 16);
            cpasync16(base + 0 * BUF + so, qkvhi + gk);
            cpasync16(base + 1 * BUF + so, qkvlo + gk);
            cpasync16(base + 2 * BUF + so, qkvhi + gv);
        }
        CP_COMMIT();
    };
    load_kv(0, 0);
    load_kv(1, 1);

    uint32_t qh[4][4], ql[4][4];
    float mr0 = -1e30f, mr1 = -1e30f, lr0 = 0.f, lr1 = 0.f;
    float oacc[8][4];
#pragma unroll
    for (int d = 0; d < 8; d++)
#pragma unroll
        for (int t = 0; t < 4; t++) oacc[d][t] = 0.f;

    for (int j = 0; j < NJT; j++) {
        int s = j % 3;
        if (j + 1 < NJT) CP_WAIT1();
        else             CP_WAIT0();
        __syncthreads();
        if (j == 0) {
#pragma unroll
            for (int ks = 0; ks < 4; ks++) {
                int row = wid * 16 + (sub & 1) * 8 + r;
                int kb  = ks * 32 + (sub >> 1) * 16;
                uint32_t so = SWZ(row * 128 + kb);
                ldm_x4(qh[ks], QHb + so);
                ldm_x4(ql[ks], QLb + so);
            }
        }
        if (j + 2 < NJT) load_kv(j + 2, (j + 2) % 3);

        uint32_t KHb = ST0 + s * 3 * BUF;
        uint32_t KLb = KHb + BUF, VHb = KLb + BUF;

        // ---- S = Q K^T (split 3-MMA) ----
        float sacc[16][4];
#pragma unroll
        for (int g = 0; g < 16; g++)
#pragma unroll
            for (int t = 0; t < 4; t++) sacc[g][t] = 0.f;

#pragma unroll
        for (int ks = 0; ks < 4; ks++) {
#pragma unroll
            for (int g = 0; g < 8; g++) {
                uint32_t bh[4], bl[4];
                int nrow = g * 16 + (sub >> 1) * 8 + r;
                int kb   = ks * 32 + (sub & 1) * 16;
                uint32_t so = SWZ(nrow * 128 + kb);
                ldm_x4(bh, KHb + so);
                ldm_x4(bl, KLb + so);
#pragma unroll
                for (int s2 = 0; s2 < 2; s2++) {
                    float* c = sacc[g * 2 + s2];
                    mma16816(c, qh[ks], &bh[s2 * 2]);
                    mma16816(c, qh[ks], &bl[s2 * 2]);
                    mma16816(c, ql[ks], &bh[s2 * 2]);
                }
            }
        }

        // ---- row max + oacc rescale ----
        float mx0 = -1e30f, mx1 = -1e30f;
#pragma unroll
        for (int g = 0; g < 16; g++) {
            mx0 = fmaxf(mx0, fmaxf(sacc[g][0], sacc[g][1]));
            mx1 = fmaxf(mx1, fmaxf(sacc[g][2], sacc[g][3]));
        }
        mx0 = fmaxf(mx0, __shfl_xor_sync(0xFFFFFFFFu, mx0, 1));
        mx0 = fmaxf(mx0, __shfl_xor_sync(0xFFFFFFFFu, mx0, 2));
        mx1 = fmaxf(mx1, __shfl_xor_sync(0xFFFFFFFFu, mx1, 1));
        mx1 = fmaxf(mx1, __shfl_xor_sync(0xFFFFFFFFu, mx1, 2));

        float mn0 = fmaxf(mr0, mx0), mn1 = fmaxf(mr1, mx1);
        float a0 = __expf(mr0 - mn0), a1 = __expf(mr1 - mn1);
        mr0 = mn0; mr1 = mn1;
#pragma unroll
        for (int d = 0; d < 8; d++) {
            oacc[d][0] *= a0; oacc[d][1] *= a0;
            oacc[d][2] *= a1; oacc[d][3] *= a1;
        }
        lr0 *= a0; lr1 *= a1;

        // ---- interleaved: exp(group) -> pack -> PV MMA, per 16-row t ----
        float sum0 = 0.f, sum1 = 0.f;
#pragma unroll
        for (int t = 0; t < 8; t++) {
            float e00 = __expf(sacc[2 * t][0] - mn0);
            float e01 = __expf(sacc[2 * t][1] - mn0);
            float e02 = __expf(sacc[2 * t][2] - mn1);
            float e03 = __expf(sacc[2 * t][3] - mn1);
            float e10 = __expf(sacc[2 * t + 1][0] - mn0);
            float e11 = __expf(sacc[2 * t + 1][1] - mn0);
            float e12 = __expf(sacc[2 * t + 1][2] - mn1);
            float e13 = __expf(sacc[2 * t + 1][3] - mn1);
            sum0 += (e00 + e01) + (e10 + e11);
            sum1 += (e02 + e03) + (e12 + e13);

            uint32_t pah[4];
            pah[0] = pack2(__float2half_rn(e00), __float2half_rn(e01));
            pah[1] = pack2(__float2half_rn(e02), __float2half_rn(e03));
            pah[2] = pack2(__float2half_rn(e10), __float2half_rn(e11));
            pah[3] = pack2(__float2half_rn(e12), __float2half_rn(e13));
#pragma unroll
            for (int gd = 0; gd < 4; gd++) {
                uint32_t vh4[4];
                int krow = t * 16 + (sub & 1) * 8 + r;
                int nb   = gd * 32 + (sub >> 1) * 16;
                ldm_x4_t(vh4, VHb + SWZ(krow * 128 + nb));
#pragma unroll
                for (int s2 = 0; s2 < 2; s2++)
                    mma16816(oacc[gd * 2 + s2], pah, &vh4[s2 * 2]);
            }
        }
        sum0 += __shfl_xor_sync(0xFFFFFFFFu, sum0, 1);
        sum0 += __shfl_xor_sync(0xFFFFFFFFu, sum0, 2);
        sum1 += __shfl_xor_sync(0xFFFFFFFFu, sum1, 1);
        sum1 += __shfl_xor_sync(0xFFFFFFFFu, sum1, 2);
        lr0 += sum0;
        lr1 += sum1;
    }

    float li0 = 1.f / lr0, li1 = 1.f / lr1;
    int qr = lane >> 2, qc = (lane & 3) * 2;
    size_t row0 = rowbase + m0 + wid * 16 + qr;
    size_t row1 = row0 + 8;
#pragma unroll
    for (int gd = 0; gd < 8; gd++) {
        int cg = zh * DH + gd * 8 + qc;
        float2 xr0 = *(const float2*)&x[row0 * EMB + cg];
        float2 xr1 = *(const float2*)&x[row1 * EMB + cg];
        float2 o0 = make_float2(oacc[gd][0] * li0 + xr0.x, oacc[gd][1] * li0 + xr0.y);
        float2 o1 = make_float2(oacc[gd][2] * li1 + xr1.x, oacc[gd][3] * li1 + xr1.y);
        *(float2*)&attn[row0 * EMB + cg] = o0;
        *(float2*)&attn[row1 * EMB + cg] = o1;
    }
}

// ============================ LayerNorm + (optional) split ============================
__global__ void ln_split_kernel(const float* __restrict__ x,
                                const float* __restrict__ gamma,
                                const float* __restrict__ beta,
                                f16* __restrict__ ohi, f16* __restrict__ olo) {
    int row = blockIdx.x;
    const float* xr = x + (size_t)row * EMB;
    int tid = threadIdx.x;
    float v[4];
    float s = 0.f, s2 = 0.f;
#pragma unroll
    for (int i = 0; i < 4; i++) {
        float t = xr[tid + i * 256];
        v[i] = t; s += t; s2 += t * t;
    }
#pragma unroll
    for (int o = 16; o > 0; o >>= 1) {
        s  += __shfl_down_sync(0xFFFFFFFFu, s,  o);
        s2 += __shfl_down_sync(0xFFFFFFFFu, s2, o);
    }
    __shared__ float rs[8], rs2[8], mu_s, rstd_s;
    int wid = tid >> 5, lane = tid & 31;
    if (lane == 0) { rs[wid] = s; rs2[wid] = s2; }
    __syncthreads();
    if (wid == 0) {
        float a  = (lane < 8) ? rs[lane]  : 0.f;
        float a2 = (lane < 8) ? rs2[lane] : 0.f;
#pragma unroll
        for (int o = 4; o > 0; o >>= 1) {
            a  += __shfl_down_sync(0xFFFFFFFFu, a,  o);
            a2 += __shfl_down_sync(0xFFFFFFFFu, a2, o);
        }
        if (lane == 0) {
            float mu = a * (1.0f / EMB);
            mu_s = mu;
            rstd_s = rsqrtf(a2 * (1.0f / EMB) - mu * mu + 1e-6f);
        }
    }
    __syncthreads();
    float mu = mu_s, rstd = rstd_s;
#pragma unroll
    for (int i = 0; i < 4; i++) {
        int c = tid + i * 256;
        float val = (v[i] - mu) * rstd * gamma[c] + beta[c];
        f16 h_, l_; split2(val, h_, l_);
        ohi[(size_t)row * EMB + c] = h_;
        if (olo) olo[(size_t)row * EMB + c] = l_;
    }
}

// ============================ combined weight prep ============================
__global__ void prep_kernel(const float* __restrict__ Wq, const float* __restrict__ Wk,
                            const float* __restrict__ Wv, const float* __restrict__ W1,
                            const float* __restrict__ W2,
                            const float* __restrict__ bq, const float* __restrict__ bk,
                            const float* __restrict__ bv,
                            f16* __restrict__ wqkvhi, f16* __restrict__ wqkvlo,
                            f16* __restrict__ w1hi, f16* __restrict__ w2hi,
                            float* __restrict__ bqkv) {
    int bid = blockIdx.x;
    int tx = threadIdx.x, ty = threadIdx.y;
    int tid = ty * 32 + tx;

    if (bid == 0) {
        for (int i = tid; i < EMB; i += 256) {
            bqkv[i]           = bq[i];
            bqkv[EMB + i]     = bk[i];
            bqkv[2 * EMB + i] = bv[i];
        }
    }

    const float* W; f16 *Thi, *Tlo; int K, N, nx, ky;
    if (bid < 3072) {
        int w = bid >> 10, t = bid & 1023;
        W = (w == 0) ? Wq : (w == 1) ? Wk : Wv;
        Thi = wqkvhi + (size_t)w * EMB * EMB;
        Tlo = wqkvlo + (size_t)w * EMB * EMB;
        K = EMB; N = EMB; nx = t & 31; ky = t >> 5;
    } else if (bid < 7168) {
        int t = bid - 3072;
        W = W1; Thi = w1hi; Tlo = nullptr;
        K = EMB; N = DFF; nx = t & 127; ky = t >> 7;
    } else {
        int t = bid - 7168;
        W = W2; Thi = w2hi; Tlo = nullptr;
        K = DFF; N = EMB; nx = t & 31; ky = t >> 5;
    }
    int n0 = nx * 32, k0 = ky * 32;

    __shared__ float tbuf[32][33];
#pragma unroll
    for (int i = ty; i < 32; i += 8)
        tbuf[i][tx] = W[(size_t)(k0 + i) * N + n0 + tx];
    __syncthreads();
#pragma unroll
    for (int i = ty; i < 32; i += 8) {
        float v = tbuf[tx][i];
        f16 h_, l_; split2(v, h_, l_);
        size_t oi = (size_t)(n0 + i) * K + k0 + tx;
        Thi[oi] = h_;
        if (Tlo) Tlo[oi] = l_;
    }
}

// ============================ launch ============================
extern "C" void kernel_launch(void* const* d_in, const int* in_sizes, int n_in,
                              void* d_out, int out_size) {
    const float* x   = (const float*)d_in[0];
    const float* Wq  = (const float*)d_in[1];
    const float* bq  = (const float*)d_in[2];
    const float* Wk  = (const float*)d_in[3];
    const float* bk  = (const float*)d_in[4];
    const float* Wv  = (const float*)d_in[5];
    const float* bv  = (const float*)d_in[6];
    const float* g1  = (const float*)d_in[7];
    const float* be1 = (const float*)d_in[8];
    const float* g2  = (const float*)d_in[9];
    const float* be2 = (const float*)d_in[10];
    const float* W1  = (const float*)d_in[11];
    const float* b1  = (const float*)d_in[12];
    const float* W2  = (const float*)d_in[13];
    const float* b2  = (const float*)d_in[14];
    float* out = (float*)d_out;

    f16 *hhi, *hlo, *wqkvhi, *wqkvlo, *w1hi, *w2hi;
    f16 *qkvhi, *qkvlo, *h2hi, *ffhi;
    float *attn, *bqkv;
    cudaGetSymbolAddress((void**)&hhi,    g_hhi);    cudaGetSymbolAddress((void**)&hlo,    g_hlo);
    cudaGetSymbolAddress((void**)&wqkvhi, g_wqkvhi); cudaGetSymbolAddress((void**)&wqkvlo, g_wqkvlo);
    cudaGetSymbolAddress((void**)&w1hi,   g_w1hi);
    cudaGetSymbolAddress((void**)&w2hi,   g_w2hi);
    cudaGetSymbolAddress((void**)&qkvhi,  g_qkvhi);  cudaGetSymbolAddress((void**)&qkvlo,  g_qkvlo);
    cudaGetSymbolAddress((void**)&attn,   g_attn);
    cudaGetSymbolAddress((void**)&h2hi,   g_h2hi);
    cudaGetSymbolAddress((void**)&ffhi,   g_ffhi);
    cudaGetSymbolAddress((void**)&bqkv,   g_bqkv);

    const int SMEM_G3 = 2 * (2 * 128 * 128 + 2 * 256 * 128);   // 196608
    const int SMEM_G1 = 3 * (128 * 128 + 256 * 128);            // 147456
    const int SMEM_F  = (2 + 9) * 16384;                        // 180224
    cudaFuncSetAttribute(gemm3_kernel, cudaFuncAttributeMaxDynamicSharedMemorySize, SMEM_G3);
    cudaFuncSetAttribute(gemm1_kernel, cudaFuncAttributeMaxDynamicSharedMemorySize, SMEM_G1);
    cudaFuncSetAttribute(fattn_kernel, cudaFuncAttributeMaxDynamicSharedMemorySize, SMEM_F);

    // 0) weight prep
    prep_kernel<<<11264, dim3(32, 8)>>>(Wq, Wk, Wv, W1, W2, bq, bk, bv,
                                        wqkvhi, wqkvlo, w1hi, w2hi, bqkv);

    // 1) LN1 -> split
    ln_split_kernel<<<TOK, 256>>>(x, g1, be1, hhi, hlo);

    // 2a) q,k projection (3-MMA split) -> packed qkv cols [0,2048)
    {
        dim3 grid(2 * EMB / 256, TOK / 128);
        gemm3_kernel<<<grid, 256, SMEM_G3>>>(hhi, hlo, wqkvhi, wqkvlo, bqkv, qkvhi, qkvlo);
    }
    // 2b) v projection (1-MMA, hi-only A) -> packed qkv cols [2048,3072)
    {
        dim3 grid(EMB / 256, TOK / 128);
        gemm1_kernel<<<grid, 256, SMEM_G1>>>(
            hhi, EMB, wqkvhi + (size_t)2 * EMB * EMB, EMB,
            bqkv + 2 * EMB, nullptr, 0,
            qkvhi + 2 * EMB, 3 * EMB, EMB, 1);
    }

    // 3) fused attention (+ residual x) -> attn
    {
        dim3 grid(SEQ / 128, BATCH * HEADS);
        fattn_kernel<<<grid, 256, SMEM_F>>>(qkvhi, qkvlo, x, attn);
    }

    // 4) LN2 -> single f16
    ln_split_kernel<<<TOK, 256>>>(attn, g2, be2, h2hi, nullptr);

    // 5) FFN1 (1-MMA, bias+gelu) -> f16
    {
        dim3 grid(DFF / 256, TOK / 128);
        gemm1_kernel<<<grid, 256, SMEM_G1>>>(h2hi, EMB, w1hi, EMB,
                                             b1, nullptr, 0, ffhi, DFF, EMB, 3);
    }

    // 6) FFN2 (1-MMA, bias + attn residual) -> d_out
    {
        dim3 grid(EMB / 256, TOK / 128);
        gemm1_kernel<<<grid, 256, SMEM_G1>>>(ffhi, DFF, w2hi, DFF,
                                             b2, attn, EMB, out, EMB, DFF, 4);
    }
}

// round 16
// speedup vs baseline: 1.0605x; 1.0547x over previous
#include <cuda_runtime.h>
#include <cuda_fp16.h>
#include <math.h>
#include <stdint.h>

#define EMB   1024
#define DFF   4096
#define HEADS 16
#define DH    64
#define BATCH 2
#define SEQ   2048
#define TOK   (BATCH*SEQ)

typedef __half f16;

// ============================ scratch (static, no allocs) ============================
__device__ __align__(1024) f16 g_hhi  [(size_t)TOK*EMB];
__device__ __align__(1024) f16 g_hlo  [(size_t)TOK*EMB];
__device__ __align__(1024) f16 g_wqkvhi[(size_t)3*EMB*EMB];   // [3072,1024] K-major
__device__ __align__(1024) f16 g_wqkvlo[(size_t)3*EMB*EMB];
__device__ __align__(1024) f16 g_w1hi [(size_t)DFF*EMB];      // [4096,1024] single
__device__ __align__(1024) f16 g_w2hi [(size_t)EMB*DFF];      // [1024,4096] single
__device__ __align__(1024) float g_bqkv[3*EMB];
__device__ __align__(1024) f16 g_qkvhi[(size_t)TOK*3*EMB];    // [tok,3072]: q|k|v (v single)
__device__ __align__(1024) f16 g_qkvlo[(size_t)TOK*3*EMB];    // lo planes for q,k only
__device__ __align__(1024) float g_attn[(size_t)TOK*EMB];
__device__ __align__(1024) f16 g_h2hi [(size_t)TOK*EMB];      // single
__device__ __align__(1024) f16 g_ffhi [(size_t)TOK*DFF];      // single (post-gelu)

// ============================ PTX helpers ============================
__device__ __forceinline__ uint32_t smem_u32(const void* p) {
    uint32_t a;
    asm("{ .reg .u64 t; cvta.to.shared.u64 t, %1; cvt.u32.u64 %0, t; }" : "=r"(a) : "l"(p));
    return a;
}
__device__ __forceinline__ void cpasync16(uint32_t dst, const void* src) {
    asm volatile("cp.async.cg.shared.global [%0], [%1], 16;\n" :: "r"(dst), "l"(src));
}
#define CP_COMMIT()  asm volatile("cp.async.commit_group;\n" ::: "memory")
#define CP_WAIT0()   asm volatile("cp.async.wait_group 0;\n" ::: "memory")
#define CP_WAIT1()   asm volatile("cp.async.wait_group 1;\n" ::: "memory")

__device__ __forceinline__ void ldm_x4(uint32_t* r, uint32_t addr) {
    asm volatile("ldmatrix.sync.aligned.m8n8.x4.shared.b16 {%0,%1,%2,%3}, [%4];"
                 : "=r"(r[0]), "=r"(r[1]), "=r"(r[2]), "=r"(r[3]) : "r"(addr));
}
__device__ __forceinline__ void ldm_x4_t(uint32_t* r, uint32_t addr) {
    asm volatile("ldmatrix.sync.aligned.m8n8.x4.trans.shared.b16 {%0,%1,%2,%3}, [%4];"
                 : "=r"(r[0]), "=r"(r[1]), "=r"(r[2]), "=r"(r[3]) : "r"(addr));
}
__device__ __forceinline__ void mma16816(float* d, const uint32_t* a, const uint32_t* b) {
    asm volatile(
        "mma.sync.aligned.m16n8k16.row.col.f32.f16.f16.f32 "
        "{%0,%1,%2,%3}, {%4,%5,%6,%7}, {%8,%9}, {%0,%1,%2,%3};"
        : "+f"(d[0]), "+f"(d[1]), "+f"(d[2]), "+f"(d[3])
        : "r"(a[0]), "r"(a[1]), "r"(a[2]), "r"(a[3]), "r"(b[0]), "r"(b[1]));
}

#define SWZ(o) ((o) ^ (((o) >> 3) & 0x70))

__device__ __forceinline__ void split2(float v, f16& hi, f16& lo) {
    hi = __float2half_rn(v);
    lo = __float2half_rn(v - __half2float(hi));
}
__device__ __forceinline__ uint32_t pack2(f16 a, f16 b) {
    __half2 h; h.x = a; h.y = b;
    return *(uint32_t*)&h;
}

// ============================ 3-MMA split GEMM (q,k projection) ============================
__global__ void __launch_bounds__(256)
gemm3_kernel(const f16* __restrict__ Ahi, const f16* __restrict__ Alo,
             const f16* __restrict__ Bhi, const f16* __restrict__ Blo,
             const float* __restrict__ bias,
             f16* __restrict__ outHi, f16* __restrict__ outLo) {
    constexpr int K = EMB, lda = EMB, ldb = EMB, ldc = 3 * EMB;
    constexpr int TN = 256;
    constexpr int ABYTES = 128 * 128;
    constexpr int BBYTES = TN * 128;
    constexpr int STAGE  = 2 * ABYTES + 2 * BBYTES;
    constexpr int WN = 64, NJ = 4;

    extern __shared__ char smem[];
    uint32_t sb = smem_u32(smem);

    int tid = threadIdx.x;
    int wid = tid >> 5, lane = tid & 31;
    int wm = wid >> 2, wn = wid & 3;
    int sub = lane >> 3, r = lane & 7;

    int m0 = blockIdx.y * 128;
    int n0 = blockIdx.x * TN;

    float acc[4][NJ * 2][4];
#pragma unroll
    for (int i = 0; i < 4; i++)
#pragma unroll
        for (int j = 0; j < NJ * 2; j++)
#pragma unroll
            for (int t = 0; t < 4; t++) acc[i][j][t] = 0.f;

    const int nIter = K / 64;

    auto load_stage = [&](int it, int s) {
        int k0 = it * 64;
        uint32_t AhB = sb + s * STAGE;
        uint32_t AlB = AhB + ABYTES;
        uint32_t BhB = AlB + ABYTES;
        uint32_t BlB = BhB + BBYTES;
#pragma unroll
        for (int t = 0; t < 4; t++) {
            int idx = tid + t * 256;
            int row = idx >> 3, seg = idx & 7;
            size_t go = (size_t)(m0 + row) * lda + k0 + seg * 8;
            uint32_t so = SWZ(row * 128 + seg * 16);
            cpasync16(AhB + so, Ahi + go);
            cpasync16(AlB + so, Alo + go);
        }
#pragma unroll
        for (int t = 0; t < 8; t++) {
            int idx = tid + t * 256;
            int row = idx >> 3, seg = idx & 7;
            size_t go = (size_t)(n0 + row) * ldb + k0 + seg * 8;
            uint32_t so = SWZ(row * 128 + seg * 16);
            cpasync16(BhB + so, Bhi + go);
            cpasync16(BlB + so, Blo + go);
        }
        CP_COMMIT();
    };

    load_stage(0, 0);

    for (int it = 0; it < nIter; it++) {
        int s = it & 1;
        CP_WAIT0();
        __syncthreads();
        if (it + 1 < nIter) load_stage(it + 1, s ^ 1);

        uint32_t AhB = sb + s * STAGE;
        uint32_t AlB = AhB + ABYTES;
        uint32_t BhB = AlB + ABYTES;
        uint32_t BlB = BhB + BBYTES;

#pragma unroll
        for (int ks = 0; ks < 4; ks++) {
            uint32_t ah[4][4], al[4][4];
#pragma unroll
            for (int mi = 0; mi < 4; mi++) {
                int row = wm * 64 + mi * 16 + (sub & 1) * 8 + r;
                int kb  = ks * 32 + (sub >> 1) * 16;
                uint32_t so = SWZ(row * 128 + kb);
                ldm_x4(ah[mi], AhB + so);
                ldm_x4(al[mi], AlB + so);
            }
#pragma unroll
            for (int j = 0; j < NJ; j++) {
                uint32_t bh[4], bl[4];
                int nrow = wn * WN + j * 16 + (sub >> 1) * 8 + r;
                int kb   = ks * 32 + (sub & 1) * 16;
                uint32_t so = SWZ(nrow * 128 + kb);
                ldm_x4(bh, BhB + so);
                ldm_x4(bl, BlB + so);
#pragma unroll
                for (int mi = 0; mi < 4; mi++)
#pragma unroll
                    for (int s2 = 0; s2 < 2; s2++) {
                        float* c = acc[mi][j * 2 + s2];
                        mma16816(c, ah[mi], &bh[s2 * 2]);
                        mma16816(c, ah[mi], &bl[s2 * 2]);
                        mma16816(c, al[mi], &bh[s2 * 2]);
                    }
            }
        }
    }

    int qr = lane >> 2;
    int qc = (lane & 3) * 2;
#pragma unroll
    for (int mi = 0; mi < 4; mi++) {
#pragma unroll
        for (int jj = 0; jj < NJ * 2; jj++) {
            int cg = n0 + wn * WN + (jj >> 1) * 16 + (jj & 1) * 8 + qc;
#pragma unroll
            for (int rr = 0; rr < 2; rr++) {
                int rg = m0 + wm * 64 + mi * 16 + qr + rr * 8;
                float c0 = acc[mi][jj][rr * 2 + 0] + bias[cg];
                float c1 = acc[mi][jj][rr * 2 + 1] + bias[cg + 1];
                size_t oi = (size_t)rg * ldc + cg;
                f16 h0, l0, h1, l1;
                split2(c0, h0, l0); split2(c1, h1, l1);
                *(uint32_t*)&outHi[oi] = pack2(h0, h1);
                *(uint32_t*)&outLo[oi] = pack2(l0, l1);
            }
        }
    }
}

// ============================ 1-MMA GEMM (FFN + v projection) ============================
// CTA tile 128x128, 3-stage, 2 CTAs/SM (reg-budgeted: acc=64 floats).
// modes: 1 bias->f16; 3 bias+gelu->f16; 4 bias+resid->fp32
__global__ void __launch_bounds__(256, 2)
gemm1_kernel(const f16* __restrict__ A, int lda,
             const f16* __restrict__ B, int ldb,
             const float* __restrict__ bias,
             const float* __restrict__ resid, int ldr,
             void* outp, int ldc, int K, int mode) {
    constexpr int TN = 128;
    constexpr int ABYTES = 128 * 128;      // 16384
    constexpr int BBYTES = TN * 128;       // 16384
    constexpr int STAGE  = ABYTES + BBYTES; // 32768 -> 3 stages = 98304
    constexpr int WN = 32, NJ = 2;

    extern __shared__ char smem[];
    uint32_t sb = smem_u32(smem);

    int tid = threadIdx.x;
    int wid = tid >> 5, lane = tid & 31;
    int wm = wid >> 2, wn = wid & 3;
    int sub = lane >> 3, r = lane & 7;

    int m0 = blockIdx.y * 128;
    int n0 = blockIdx.x * TN;

    float acc[4][NJ * 2][4];    // 64 floats
#pragma unroll
    for (int i = 0; i < 4; i++)
#pragma unroll
        for (int j = 0; j < NJ * 2; j++)
#pragma unroll
            for (int t = 0; t < 4; t++) acc[i][j][t] = 0.f;

    const int nIter = K / 64;

    auto load_stage = [&](int it, int s) {
        int k0 = it * 64;
        uint32_t AB = sb + s * STAGE;
        uint32_t BB = AB + ABYTES;
#pragma unroll
        for (int t = 0; t < 4; t++) {
            int idx = tid + t * 256;
            int row = idx >> 3, seg = idx & 7;
            size_t go = (size_t)(m0 + row) * lda + k0 + seg * 8;
            cpasync16(AB + SWZ(row * 128 + seg * 16), A + go);
        }
#pragma unroll
        for (int t = 0; t < 4; t++) {
            int idx = tid + t * 256;
            int row = idx >> 3, seg = idx & 7;
            size_t go = (size_t)(n0 + row) * ldb + k0 + seg * 8;
            cpasync16(BB + SWZ(row * 128 + seg * 16), B + go);
        }
        CP_COMMIT();
    };

    load_stage(0, 0);
    load_stage(1, 1);

    for (int it = 0; it < nIter; it++) {
        int s = it % 3;
        if (it + 1 < nIter) CP_WAIT1();
        else                CP_WAIT0();
        __syncthreads();
        if (it + 2 < nIter) load_stage(it + 2, (it + 2) % 3);

        uint32_t AB = sb + s * STAGE;
        uint32_t BB = AB + ABYTES;

#pragma unroll
        for (int ks = 0; ks < 4; ks++) {
            uint32_t a4[4][4];
#pragma unroll
            for (int mi = 0; mi < 4; mi++) {
                int row = wm * 64 + mi * 16 + (sub & 1) * 8 + r;
                int kb  = ks * 32 + (sub >> 1) * 16;
                ldm_x4(a4[mi], AB + SWZ(row * 128 + kb));
            }
#pragma unroll
            for (int j = 0; j < NJ; j++) {
                uint32_t b4[4];
                int nrow = wn * WN + j * 16 + (sub >> 1) * 8 + r;
                int kb   = ks * 32 + (sub & 1) * 16;
                ldm_x4(b4, BB + SWZ(nrow * 128 + kb));
#pragma unroll
                for (int mi = 0; mi < 4; mi++)
#pragma unroll
                    for (int s2 = 0; s2 < 2; s2++)
                        mma16816(acc[mi][j * 2 + s2], a4[mi], &b4[s2 * 2]);
            }
        }
    }

    int qr = lane >> 2;
    int qc = (lane & 3) * 2;
#pragma unroll
    for (int mi = 0; mi < 4; mi++) {
#pragma unroll
        for (int jj = 0; jj < NJ * 2; jj++) {
            int cg = n0 + wn * WN + (jj >> 1) * 16 + (jj & 1) * 8 + qc;
#pragma unroll
            for (int rr = 0; rr < 2; rr++) {
                int rg = m0 + wm * 64 + mi * 16 + qr + rr * 8;
                float c0 = acc[mi][jj][rr * 2 + 0] + bias[cg];
                float c1 = acc[mi][jj][rr * 2 + 1] + bias[cg + 1];
                if (mode == 4) {
                    c0 += resid[(size_t)rg * ldr + cg];
                    c1 += resid[(size_t)rg * ldr + cg + 1];
                    float* o = (float*)outp;
                    *(float2*)&o[(size_t)rg * ldc + cg] = make_float2(c0, c1);
                } else {
                    if (mode == 3) {
                        c0 = 0.5f * c0 * (1.0f + erff(c0 * 0.70710678118654752f));
                        c1 = 0.5f * c1 * (1.0f + erff(c1 * 0.70710678118654752f));
                    }
                    f16* o = (f16*)outp;
                    *(uint32_t*)&o[(size_t)rg * ldc + cg] =
                        pack2(__float2half_rn(c0), __float2half_rn(c1));
                }
            }
        }
    }
}

// ============================ fused flash attention, 3-stage KV ============================
__global__ void __launch_bounds__(256)
fattn_kernel(const f16* __restrict__ qkvhi, const f16* __restrict__ qkvlo,
             const float* __restrict__ x, float* __restrict__ attn) {
    constexpr int BUF = 128 * 128;
    constexpr int LD  = 3 * EMB;
    constexpr int NJT = SEQ / 128;
    extern __shared__ char smem[];
    uint32_t sb = smem_u32(smem);
    const uint32_t QHb = sb, QLb = sb + BUF;
    const uint32_t ST0 = sb + 2 * BUF;

    int tid = threadIdx.x, wid = tid >> 5, lane = tid & 31;
    int sub = lane >> 3, r = lane & 7;
    int z = blockIdx.y, zb = z >> 4, zh = z & 15;
    int m0 = blockIdx.x * 128;

    const size_t rowbase = (size_t)zb * SEQ;
    const int qcol = zh * DH, kcol = EMB + zh * DH, vcol = 2 * EMB + zh * DH;

#pragma unroll
    for (int t = 0; t < 4; t++) {
        int idx = tid + t * 256;
        int row = idx >> 3, seg = idx & 7;
        size_t go = (rowbase + m0 + row) * LD + qcol + seg * 8;
        uint32_t so = SWZ(row * 128 + seg * 16);
        cpasync16(QHb + so, qkvhi + go);
        cpasync16(QLb + so, qkvlo + go);
    }
    CP_COMMIT();
    auto load_kv = [&](int j, int s) {
        uint32_t base = ST0 + s * 3 * BUF;
        int k0 = j * 128;
#pragma unroll
        for (int t = 0; t < 4; t++) {
            int idx = tid + t * 256;
            int row = idx >> 3, seg = idx & 7;
            size_t gk = (rowbase + k0 + row) * LD + kcol + seg * 8;
            size_t gv = (rowbase + k0 + row) * LD + vcol + seg * 8;
            uint32_t so = SWZ(row * 128 + seg * 16);
            cpasync16(base + 0 * BUF + so, qkvhi + gk);
            cpasync16(base + 1 * BUF + so, qkvlo + gk);
            cpasync16(base + 2 * BUF + so, qkvhi + gv);
        }
        CP_COMMIT();
    };
    load_kv(0, 0);
    load_kv(1, 1);

    uint32_t qh[4][4], ql[4][4];
    float mr0 = -1e30f, mr1 = -1e30f, lr0 = 0.f, lr1 = 0.f;
    float oacc[8][4];
#pragma unroll
    for (int d = 0; d < 8; d++)
#pragma unroll
        for (int t = 0; t < 4; t++) oacc[d][t] = 0.f;

    for (int j = 0; j < NJT; j++) {
        int s = j % 3;
        if (j + 1 < NJT) CP_WAIT1();
        else             CP_WAIT0();
        __syncthreads();
        if (j == 0) {
#pragma unroll
            for (int ks = 0; ks < 4; ks++) {
                int row = wid * 16 + (sub & 1) * 8 + r;
                int kb  = ks * 32 + (sub >> 1) * 16;
                uint32_t so = SWZ(row * 128 + kb);
                ldm_x4(qh[ks], QHb + so);
                ldm_x4(ql[ks], QLb + so);
            }
        }
        if (j + 2 < NJT) load_kv(j + 2, (j + 2) % 3);

        uint32_t KHb = ST0 + s * 3 * BUF;
        uint32_t KLb = KHb + BUF, VHb = KLb + BUF;

        float sacc[16][4];
#pragma unroll
        for (int g = 0; g < 16; g++)
#pragma unroll
            for (int t = 0; t < 4; t++) sacc[g][t] = 0.f;

#pragma unroll
        for (int ks = 0; ks < 4; ks++) {
#pragma unroll
            for (int g = 0; g < 8; g++) {
                uint32_t bh[4], bl[4];
                int nrow = g * 16 + (sub >> 1) * 8 + r;
                int kb   = ks * 32 + (sub & 1) * 16;
                uint32_t so = SWZ(nrow * 128 + kb);
                ldm_x4(bh, KHb + so);
                ldm_x4(bl, KLb + so);
#pragma unroll
                for (int s2 = 0; s2 < 2; s2++) {
                    float* c = sacc[g * 2 + s2];
                    mma16816(c, qh[ks], &bh[s2 * 2]);
                    mma16816(c, qh[ks], &bl[s2 * 2]);
                    mma16816(c, ql[ks], &bh[s2 * 2]);
                }
            }
        }

        float mx0 = -1e30f, mx1 = -1e30f;
#pragma unroll
        for (int g = 0; g < 16; g++) {
            mx0 = fmaxf(mx0, fmaxf(sacc[g][0], sacc[g][1]));
            mx1 = fmaxf(mx1, fmaxf(sacc[g][2], sacc[g][3]));
        }
        mx0 = fmaxf(mx0, __shfl_xor_sync(0xFFFFFFFFu, mx0, 1));
        mx0 = fmaxf(mx0, __shfl_xor_sync(0xFFFFFFFFu, mx0, 2));
        mx1 = fmaxf(mx1, __shfl_xor_sync(0xFFFFFFFFu, mx1, 1));
        mx1 = fmaxf(mx1, __shfl_xor_sync(0xFFFFFFFFu, mx1, 2));

        float mn0 = fmaxf(mr0, mx0), mn1 = fmaxf(mr1, mx1);
        float a0 = __expf(mr0 - mn0), a1 = __expf(mr1 - mn1);
        mr0 = mn0; mr1 = mn1;
#pragma unroll
        for (int d = 0; d < 8; d++) {
            oacc[d][0] *= a0; oacc[d][1] *= a0;
            oacc[d][2] *= a1; oacc[d][3] *= a1;
        }
        lr0 *= a0; lr1 *= a1;

        float sum0 = 0.f, sum1 = 0.f;
#pragma unroll
        for (int t = 0; t < 8; t++) {
            float e00 = __expf(sacc[2 * t][0] - mn0);
            float e01 = __expf(sacc[2 * t][1] - mn0);
            float e02 = __expf(sacc[2 * t][2] - mn1);
            float e03 = __expf(sacc[2 * t][3] - mn1);
            float e10 = __expf(sacc[2 * t + 1][0] - mn0);
            float e11 = __expf(sacc[2 * t + 1][1] - mn0);
            float e12 = __expf(sacc[2 * t + 1][2] - mn1);
            float e13 = __expf(sacc[2 * t + 1][3] - mn1);
            sum0 += (e00 + e01) + (e10 + e11);
            sum1 += (e02 + e03) + (e12 + e13);

            uint32_t pah[4];
            pah[0] = pack2(__float2half_rn(e00), __float2half_rn(e01));
            pah[1] = pack2(__float2half_rn(e02), __float2half_rn(e03));
            pah[2] = pack2(__float2half_rn(e10), __float2half_rn(e11));
            pah[3] = pack2(__float2half_rn(e12), __float2half_rn(e13));
#pragma unroll
            for (int gd = 0; gd < 4; gd++) {
                uint32_t vh4[4];
                int krow = t * 16 + (sub & 1) * 8 + r;
                int nb   = gd * 32 + (sub >> 1) * 16;
                ldm_x4_t(vh4, VHb + SWZ(krow * 128 + nb));
#pragma unroll
                for (int s2 = 0; s2 < 2; s2++)
                    mma16816(oacc[gd * 2 + s2], pah, &vh4[s2 * 2]);
            }
        }
        sum0 += __shfl_xor_sync(0xFFFFFFFFu, sum0, 1);
        sum0 += __shfl_xor_sync(0xFFFFFFFFu, sum0, 2);
        sum1 += __shfl_xor_sync(0xFFFFFFFFu, sum1, 1);
        sum1 += __shfl_xor_sync(0xFFFFFFFFu, sum1, 2);
        lr0 += sum0;
        lr1 += sum1;
    }

    float li0 = 1.f / lr0, li1 = 1.f / lr1;
    int qr = lane >> 2, qc = (lane & 3) * 2;
    size_t row0 = rowbase + m0 + wid * 16 + qr;
    size_t row1 = row0 + 8;
#pragma unroll
    for (int gd = 0; gd < 8; gd++) {
        int cg = zh * DH + gd * 8 + qc;
        float2 xr0 = *(const float2*)&x[row0 * EMB + cg];
        float2 xr1 = *(const float2*)&x[row1 * EMB + cg];
        float2 o0 = make_float2(oacc[gd][0] * li0 + xr0.x, oacc[gd][1] * li0 + xr0.y);
        float2 o1 = make_float2(oacc[gd][2] * li1 + xr1.x, oacc[gd][3] * li1 + xr1.y);
        *(float2*)&attn[row0 * EMB + cg] = o0;
        *(float2*)&attn[row1 * EMB + cg] = o1;
    }
}

// ============================ LayerNorm + (optional) split ============================
__global__ void ln_split_kernel(const float* __restrict__ x,
                                const float* __restrict__ gamma,
                                const float* __restrict__ beta,
                                f16* __restrict__ ohi, f16* __restrict__ olo) {
    int row = blockIdx.x;
    const float* xr = x + (size_t)row * EMB;
    int tid = threadIdx.x;
    float v[4];
    float s = 0.f, s2 = 0.f;
#pragma unroll
    for (int i = 0; i < 4; i++) {
        float t = xr[tid + i * 256];
        v[i] = t; s += t; s2 += t * t;
    }
#pragma unroll
    for (int o = 16; o > 0; o >>= 1) {
        s  += __shfl_down_sync(0xFFFFFFFFu, s,  o);
        s2 += __shfl_down_sync(0xFFFFFFFFu, s2, o);
    }
    __shared__ float rs[8], rs2[8], mu_s, rstd_s;
    int wid = tid >> 5, lane = tid & 31;
    if (lane == 0) { rs[wid] = s; rs2[wid] = s2; }
    __syncthreads();
    if (wid == 0) {
        float a  = (lane < 8) ? rs[lane]  : 0.f;
        float a2 = (lane < 8) ? rs2[lane] : 0.f;
#pragma unroll
        for (int o = 4; o > 0; o >>= 1) {
            a  += __shfl_down_sync(0xFFFFFFFFu, a,  o);
            a2 += __shfl_down_sync(0xFFFFFFFFu, a2, o);
        }
        if (lane == 0) {
            float mu = a * (1.0f / EMB);
            mu_s = mu;
            rstd_s = rsqrtf(a2 * (1.0f / EMB) - mu * mu + 1e-6f);
        }
    }
    __syncthreads();
    float mu = mu_s, rstd = rstd_s;
#pragma unroll
    for (int i = 0; i < 4; i++) {
        int c = tid + i * 256;
        float val = (v[i] - mu) * rstd * gamma[c] + beta[c];
        f16 h_, l_; split2(val, h_, l_);
        ohi[(size_t)row * EMB + c] = h_;
        if (olo) olo[(size_t)row * EMB + c] = l_;
    }
}

// ============================ combined weight prep ============================
__global__ void prep_kernel(const float* __restrict__ Wq, const float* __restrict__ Wk,
                            const float* __restrict__ Wv, const float* __restrict__ W1,
                            const float* __restrict__ W2,
                            const float* __restrict__ bq, const float* __restrict__ bk,
                            const float* __restrict__ bv,
                            f16* __restrict__ wqkvhi, f16* __restrict__ wqkvlo,
                            f16* __restrict__ w1hi, f16* __restrict__ w2hi,
                            float* __restrict__ bqkv) {
    int bid = blockIdx.x;
    int tx = threadIdx.x, ty = threadIdx.y;
    int tid = ty * 32 + tx;

    if (bid == 0) {
        for (int i = tid; i < EMB; i += 256) {
            bqkv[i]           = bq[i];
            bqkv[EMB + i]     = bk[i];
            bqkv[2 * EMB + i] = bv[i];
        }
    }

    const float* W; f16 *Thi, *Tlo; int K, N, nx, ky;
    if (bid < 3072) {
        int w = bid >> 10, t = bid & 1023;
        W = (w == 0) ? Wq : (w == 1) ? Wk : Wv;
        Thi = wqkvhi + (size_t)w * EMB * EMB;
        Tlo = wqkvlo + (size_t)w * EMB * EMB;
        K = EMB; N = EMB; nx = t & 31; ky = t >> 5;
    } else if (bid < 7168) {
        int t = bid - 3072;
        W = W1; Thi = w1hi; Tlo = nullptr;
        K = EMB; N = DFF; nx = t & 127; ky = t >> 7;
    } else {
        int t = bid - 7168;
        W = W2; Thi = w2hi; Tlo = nullptr;
        K = DFF; N = EMB; nx = t & 31; ky = t >> 5;
    }
    int n0 = nx * 32, k0 = ky * 32;

    __shared__ float tbuf[32][33];
#pragma unroll
    for (int i = ty; i < 32; i += 8)
        tbuf[i][tx] = W[(size_t)(k0 + i) * N + n0 + tx];
    __syncthreads();
#pragma unroll
    for (int i = ty; i < 32; i += 8) {
        float v = tbuf[tx][i];
        f16 h_, l_; split2(v, h_, l_);
        size_t oi = (size_t)(n0 + i) * K + k0 + tx;
        Thi[oi] = h_;
        if (Tlo) Tlo[oi] = l_;
    }
}

// ============================ launch ============================
extern "C" void kernel_launch(void* const* d_in, const int* in_sizes, int n_in,
                              void* d_out, int out_size) {
    const float* x   = (const float*)d_in[0];
    const float* Wq  = (const float*)d_in[1];
    const float* bq  = (const float*)d_in[2];
    const float* Wk  = (const float*)d_in[3];
    const float* bk  = (const float*)d_in[4];
    const float* Wv  = (const float*)d_in[5];
    const float* bv  = (const float*)d_in[6];
    const float* g1  = (const float*)d_in[7];
    const float* be1 = (const float*)d_in[8];
    const float* g2  = (const float*)d_in[9];
    const float* be2 = (const float*)d_in[10];
    const float* W1  = (const float*)d_in[11];
    const float* b1  = (const float*)d_in[12];
    const float* W2  = (const float*)d_in[13];
    const float* b2  = (const float*)d_in[14];
    float* out = (float*)d_out;

    f16 *hhi, *hlo, *wqkvhi, *wqkvlo, *w1hi, *w2hi;
    f16 *qkvhi, *qkvlo, *h2hi, *ffhi;
    float *attn, *bqkv;
    cudaGetSymbolAddress((void**)&hhi,    g_hhi);    cudaGetSymbolAddress((void**)&hlo,    g_hlo);
    cudaGetSymbolAddress((void**)&wqkvhi, g_wqkvhi); cudaGetSymbolAddress((void**)&wqkvlo, g_wqkvlo);
    cudaGetSymbolAddress((void**)&w1hi,   g_w1hi);
    cudaGetSymbolAddress((void**)&w2hi,   g_w2hi);
    cudaGetSymbolAddress((void**)&qkvhi,  g_qkvhi);  cudaGetSymbolAddress((void**)&qkvlo,  g_qkvlo);
    cudaGetSymbolAddress((void**)&attn,   g_attn);
    cudaGetSymbolAddress((void**)&h2hi,   g_h2hi);
    cudaGetSymbolAddress((void**)&ffhi,   g_ffhi);
    cudaGetSymbolAddress((void**)&bqkv,   g_bqkv);

    const int SMEM_G3 = 2 * (2 * 128 * 128 + 2 * 256 * 128);   // 196608
    const int SMEM_G1 = 3 * (128 * 128 + 128 * 128);            //  98304 (128-wide, 3-stage)
    const int SMEM_F  = (2 + 9) * 16384;                        // 180224
    cudaFuncSetAttribute(gemm3_kernel, cudaFuncAttributeMaxDynamicSharedMemorySize, SMEM_G3);
    cudaFuncSetAttribute(gemm1_kernel, cudaFuncAttributeMaxDynamicSharedMemorySize, SMEM_G1);
    cudaFuncSetAttribute(fattn_kernel, cudaFuncAttributeMaxDynamicSharedMemorySize, SMEM_F);

    // 0) weight prep
    prep_kernel<<<11264, dim3(32, 8)>>>(Wq, Wk, Wv, W1, W2, bq, bk, bv,
                                        wqkvhi, wqkvlo, w1hi, w2hi, bqkv);

    // 1) LN1 -> split
    ln_split_kernel<<<TOK, 256>>>(x, g1, be1, hhi, hlo);

    // 2a) q,k projection (3-MMA split) -> packed qkv cols [0,2048)
    {
        dim3 grid(2 * EMB / 256, TOK / 128);
        gemm3_kernel<<<grid, 256, SMEM_G3>>>(hhi, hlo, wqkvhi, wqkvlo, bqkv, qkvhi, qkvlo);
    }
    // 2b) v projection (1-MMA, hi-only A) -> packed qkv cols [2048,3072)
    {
        dim3 grid(EMB / 128, TOK / 128);
        gemm1_kernel<<<grid, 256, SMEM_G1>>>(
            hhi, EMB, wqkvhi + (size_t)2 * EMB * EMB, EMB,
            bqkv + 2 * EMB, nullptr, 0,
            qkvhi + 2 * EMB, 3 * EMB, EMB, 1);
    }

    // 3) fused attention (+ residual x) -> attn
    {
        dim3 grid(SEQ / 128, BATCH * HEADS);
        fattn_kernel<<<grid, 256, SMEM_F>>>(qkvhi, qkvlo, x, attn);
    }

    // 4) LN2 -> single f16
    ln_split_kernel<<<TOK, 256>>>(attn, g2, be2, h2hi, nullptr);

    // 5) FFN1 (1-MMA, bias+gelu) -> f16
    {
        dim3 grid(DFF / 128, TOK / 128);
        gemm1_kernel<<<grid, 256, SMEM_G1>>>(h2hi, EMB, w1hi, EMB,
                                             b1, nullptr, 0, ffhi, DFF, EMB, 3);
    }

    // 6) FFN2 (1-MMA, bias + attn residual) -> d_out
    {
        dim3 grid(EMB / 128, TOK / 128);
        gemm1_kernel<<<grid, 256, SMEM_G1>>>(ffhi, DFF, w2hi, DFF,
                                             b2, attn, EMB, out, EMB, DFF, 4);
    }
}

// round 17
// speedup vs baseline: 1.1327x; 1.0680x over previous
#include <cuda_runtime.h>
#include <cuda_fp16.h>
#include <math.h>
#include <stdint.h>

#define EMB   1024
#define DFF   4096
#define HEADS 16
#define DH    64
#define BATCH 2
#define SEQ   2048
#define TOK   (BATCH*SEQ)

typedef __half f16;

// ============================ scratch (static, no allocs) ============================
__device__ __align__(1024) f16 g_hhi  [(size_t)TOK*EMB];
__device__ __align__(1024) f16 g_hlo  [(size_t)TOK*EMB];
__device__ __align__(1024) f16 g_wqkvhi[(size_t)3*EMB*EMB];   // [3072,1024] K-major
__device__ __align__(1024) f16 g_wqkvlo[(size_t)3*EMB*EMB];
__device__ __align__(1024) f16 g_w1hi [(size_t)DFF*EMB];      // [4096,1024] single
__device__ __align__(1024) f16 g_w2hi [(size_t)EMB*DFF];      // [1024,4096] single
__device__ __align__(1024) float g_bqkv[3*EMB];
__device__ __align__(1024) f16 g_qkvhi[(size_t)TOK*3*EMB];    // [tok,3072]: q|k|v (v single)
__device__ __align__(1024) f16 g_qkvlo[(size_t)TOK*3*EMB];    // lo planes for q,k only
__device__ __align__(1024) float g_attn[(size_t)TOK*EMB];
__device__ __align__(1024) f16 g_h2hi [(size_t)TOK*EMB];      // single
__device__ __align__(1024) f16 g_ffhi [(size_t)TOK*DFF];      // single (post-gelu)

// ============================ PTX helpers ============================
__device__ __forceinline__ uint32_t smem_u32(const void* p) {
    uint32_t a;
    asm("{ .reg .u64 t; cvta.to.shared.u64 t, %1; cvt.u32.u64 %0, t; }" : "=r"(a) : "l"(p));
    return a;
}
__device__ __forceinline__ void cpasync16(uint32_t dst, const void* src) {
    asm volatile("cp.async.cg.shared.global [%0], [%1], 16;\n" :: "r"(dst), "l"(src));
}
#define CP_COMMIT()  asm volatile("cp.async.commit_group;\n" ::: "memory")
#define CP_WAIT0()   asm volatile("cp.async.wait_group 0;\n" ::: "memory")
#define CP_WAIT1()   asm volatile("cp.async.wait_group 1;\n" ::: "memory")

__device__ __forceinline__ void ldm_x4(uint32_t* r, uint32_t addr) {
    asm volatile("ldmatrix.sync.aligned.m8n8.x4.shared.b16 {%0,%1,%2,%3}, [%4];"
                 : "=r"(r[0]), "=r"(r[1]), "=r"(r[2]), "=r"(r[3]) : "r"(addr));
}
__device__ __forceinline__ void ldm_x4_t(uint32_t* r, uint32_t addr) {
    asm volatile("ldmatrix.sync.aligned.m8n8.x4.trans.shared.b16 {%0,%1,%2,%3}, [%4];"
                 : "=r"(r[0]), "=r"(r[1]), "=r"(r[2]), "=r"(r[3]) : "r"(addr));
}
__device__ __forceinline__ void mma16816(float* d, const uint32_t* a, const uint32_t* b) {
    asm volatile(
        "mma.sync.aligned.m16n8k16.row.col.f32.f16.f16.f32 "
        "{%0,%1,%2,%3}, {%4,%5,%6,%7}, {%8,%9}, {%0,%1,%2,%3};"
        : "+f"(d[0]), "+f"(d[1]), "+f"(d[2]), "+f"(d[3])
        : "r"(a[0]), "r"(a[1]), "r"(a[2]), "r"(a[3]), "r"(b[0]), "r"(b[1]));
}

#define SWZ(o) ((o) ^ (((o) >> 3) & 0x70))

__device__ __forceinline__ void split2(float v, f16& hi, f16& lo) {
    hi = __float2half_rn(v);
    lo = __float2half_rn(v - __half2float(hi));
}
__device__ __forceinline__ uint32_t pack2(f16 a, f16 b) {
    __half2 h; h.x = a; h.y = b;
    return *(uint32_t*)&h;
}

// ============================ 3-MMA split GEMM (q,k projection) ============================
__global__ void __launch_bounds__(256)
gemm3_kernel(const f16* __restrict__ Ahi, const f16* __restrict__ Alo,
             const f16* __restrict__ Bhi, const f16* __restrict__ Blo,
             const float* __restrict__ bias,
             f16* __restrict__ outHi, f16* __restrict__ outLo) {
    constexpr int K = EMB, lda = EMB, ldb = EMB, ldc = 3 * EMB;
    constexpr int TN = 256;
    constexpr int ABYTES = 128 * 128;
    constexpr int BBYTES = TN * 128;
    constexpr int STAGE  = 2 * ABYTES + 2 * BBYTES;
    constexpr int WN = 64, NJ = 4;

    extern __shared__ char smem[];
    uint32_t sb = smem_u32(smem);

    int tid = threadIdx.x;
    int wid = tid >> 5, lane = tid & 31;
    int wm = wid >> 2, wn = wid & 3;
    int sub = lane >> 3, r = lane & 7;

    int m0 = blockIdx.y * 128;
    int n0 = blockIdx.x * TN;

    float acc[4][NJ * 2][4];
#pragma unroll
    for (int i = 0; i < 4; i++)
#pragma unroll
        for (int j = 0; j < NJ * 2; j++)
#pragma unroll
            for (int t = 0; t < 4; t++) acc[i][j][t] = 0.f;

    const int nIter = K / 64;

    auto load_stage = [&](int it, int s) {
        int k0 = it * 64;
        uint32_t AhB = sb + s * STAGE;
        uint32_t AlB = AhB + ABYTES;
        uint32_t BhB = AlB + ABYTES;
        uint32_t BlB = BhB + BBYTES;
#pragma unroll
        for (int t = 0; t < 4; t++) {
            int idx = tid + t * 256;
            int row = idx >> 3, seg = idx & 7;
            size_t go = (size_t)(m0 + row) * lda + k0 + seg * 8;
            uint32_t so = SWZ(row * 128 + seg * 16);
            cpasync16(AhB + so, Ahi + go);
            cpasync16(AlB + so, Alo + go);
        }
#pragma unroll
        for (int t = 0; t < 8; t++) {
            int idx = tid + t * 256;
            int row = idx >> 3, seg = idx & 7;
            size_t go = (size_t)(n0 + row) * ldb + k0 + seg * 8;
            uint32_t so = SWZ(row * 128 + seg * 16);
            cpasync16(BhB + so, Bhi + go);
            cpasync16(BlB + so, Blo + go);
        }
        CP_COMMIT();
    };

    load_stage(0, 0);

    for (int it = 0; it < nIter; it++) {
        int s = it & 1;
        CP_WAIT0();
        __syncthreads();
        if (it + 1 < nIter) load_stage(it + 1, s ^ 1);

        uint32_t AhB = sb + s * STAGE;
        uint32_t AlB = AhB + ABYTES;
        uint32_t BhB = AlB + ABYTES;
        uint32_t BlB = BhB + BBYTES;

#pragma unroll
        for (int ks = 0; ks < 4; ks++) {
            uint32_t ah[4][4], al[4][4];
#pragma unroll
            for (int mi = 0; mi < 4; mi++) {
                int row = wm * 64 + mi * 16 + (sub & 1) * 8 + r;
                int kb  = ks * 32 + (sub >> 1) * 16;
                uint32_t so = SWZ(row * 128 + kb);
                ldm_x4(ah[mi], AhB + so);
                ldm_x4(al[mi], AlB + so);
            }
#pragma unroll
            for (int j = 0; j < NJ; j++) {
                uint32_t bh[4], bl[4];
                int nrow = wn * WN + j * 16 + (sub >> 1) * 8 + r;
                int kb   = ks * 32 + (sub & 1) * 16;
                uint32_t so = SWZ(nrow * 128 + kb);
                ldm_x4(bh, BhB + so);
                ldm_x4(bl, BlB + so);
#pragma unroll
                for (int mi = 0; mi < 4; mi++)
#pragma unroll
                    for (int s2 = 0; s2 < 2; s2++) {
                        float* c = acc[mi][j * 2 + s2];
                        mma16816(c, ah[mi], &bh[s2 * 2]);
                        mma16816(c, ah[mi], &bl[s2 * 2]);
                        mma16816(c, al[mi], &bh[s2 * 2]);
                    }
            }
        }
    }

    int qr = lane >> 2;
    int qc = (lane & 3) * 2;
#pragma unroll
    for (int mi = 0; mi < 4; mi++) {
#pragma unroll
        for (int jj = 0; jj < NJ * 2; jj++) {
            int cg = n0 + wn * WN + (jj >> 1) * 16 + (jj & 1) * 8 + qc;
#pragma unroll
            for (int rr = 0; rr < 2; rr++) {
                int rg = m0 + wm * 64 + mi * 16 + qr + rr * 8;
                float c0 = acc[mi][jj][rr * 2 + 0] + bias[cg];
                float c1 = acc[mi][jj][rr * 2 + 1] + bias[cg + 1];
                size_t oi = (size_t)rg * ldc + cg;
                f16 h0, l0, h1, l1;
                split2(c0, h0, l0); split2(c1, h1, l1);
                *(uint32_t*)&outHi[oi] = pack2(h0, h1);
                *(uint32_t*)&outLo[oi] = pack2(l0, l1);
            }
        }
    }
}

// ============================ 1-MMA GEMM (FFN + v projection) ============================
// CTA tile 128x128, 3-stage, 2 CTAs/SM.
__global__ void __launch_bounds__(256, 2)
gemm1_kernel(const f16* __restrict__ A, int lda,
             const f16* __restrict__ B, int ldb,
             const float* __restrict__ bias,
             const float* __restrict__ resid, int ldr,
             void* outp, int ldc, int K, int mode) {
    constexpr int TN = 128;
    constexpr int ABYTES = 128 * 128;
    constexpr int BBYTES = TN * 128;
    constexpr int STAGE  = ABYTES + BBYTES;
    constexpr int WN = 32, NJ = 2;

    extern __shared__ char smem[];
    uint32_t sb = smem_u32(smem);

    int tid = threadIdx.x;
    int wid = tid >> 5, lane = tid & 31;
    int wm = wid >> 2, wn = wid & 3;
    int sub = lane >> 3, r = lane & 7;

    int m0 = blockIdx.y * 128;
    int n0 = blockIdx.x * TN;

    float acc[4][NJ * 2][4];
#pragma unroll
    for (int i = 0; i < 4; i++)
#pragma unroll
        for (int j = 0; j < NJ * 2; j++)
#pragma unroll
            for (int t = 0; t < 4; t++) acc[i][j][t] = 0.f;

    const int nIter = K / 64;

    auto load_stage = [&](int it, int s) {
        int k0 = it * 64;
        uint32_t AB = sb + s * STAGE;
        uint32_t BB = AB + ABYTES;
#pragma unroll
        for (int t = 0; t < 4; t++) {
            int idx = tid + t * 256;
            int row = idx >> 3, seg = idx & 7;
            size_t go = (size_t)(m0 + row) * lda + k0 + seg * 8;
            cpasync16(AB + SWZ(row * 128 + seg * 16), A + go);
        }
#pragma unroll
        for (int t = 0; t < 4; t++) {
            int idx = tid + t * 256;
            int row = idx >> 3, seg = idx & 7;
            size_t go = (size_t)(n0 + row) * ldb + k0 + seg * 8;
            cpasync16(BB + SWZ(row * 128 + seg * 16), B + go);
        }
        CP_COMMIT();
    };

    load_stage(0, 0);
    load_stage(1, 1);

    for (int it = 0; it < nIter; it++) {
        int s = it % 3;
        if (it + 1 < nIter) CP_WAIT1();
        else                CP_WAIT0();
        __syncthreads();
        if (it + 2 < nIter) load_stage(it + 2, (it + 2) % 3);

        uint32_t AB = sb + s * STAGE;
        uint32_t BB = AB + ABYTES;

#pragma unroll
        for (int ks = 0; ks < 4; ks++) {
            uint32_t a4[4][4];
#pragma unroll
            for (int mi = 0; mi < 4; mi++) {
                int row = wm * 64 + mi * 16 + (sub & 1) * 8 + r;
                int kb  = ks * 32 + (sub >> 1) * 16;
                ldm_x4(a4[mi], AB + SWZ(row * 128 + kb));
            }
#pragma unroll
            for (int j = 0; j < NJ; j++) {
                uint32_t b4[4];
                int nrow = wn * WN + j * 16 + (sub >> 1) * 8 + r;
                int kb   = ks * 32 + (sub & 1) * 16;
                ldm_x4(b4, BB + SWZ(nrow * 128 + kb));
#pragma unroll
                for (int mi = 0; mi < 4; mi++)
#pragma unroll
                    for (int s2 = 0; s2 < 2; s2++)
                        mma16816(acc[mi][j * 2 + s2], a4[mi], &b4[s2 * 2]);
            }
        }
    }

    int qr = lane >> 2;
    int qc = (lane & 3) * 2;
#pragma unroll
    for (int mi = 0; mi < 4; mi++) {
#pragma unroll
        for (int jj = 0; jj < NJ * 2; jj++) {
            int cg = n0 + wn * WN + (jj >> 1) * 16 + (jj & 1) * 8 + qc;
#pragma unroll
            for (int rr = 0; rr < 2; rr++) {
                int rg = m0 + wm * 64 + mi * 16 + qr + rr * 8;
                float c0 = acc[mi][jj][rr * 2 + 0] + bias[cg];
                float c1 = acc[mi][jj][rr * 2 + 1] + bias[cg + 1];
                if (mode == 4) {
                    c0 += resid[(size_t)rg * ldr + cg];
                    c1 += resid[(size_t)rg * ldr + cg + 1];
                    float* o = (float*)outp;
                    *(float2*)&o[(size_t)rg * ldc + cg] = make_float2(c0, c1);
                } else {
                    if (mode == 3) {
                        c0 = 0.5f * c0 * (1.0f + erff(c0 * 0.70710678118654752f));
                        c1 = 0.5f * c1 * (1.0f + erff(c1 * 0.70710678118654752f));
                    }
                    f16* o = (f16*)outp;
                    *(uint32_t*)&o[(size_t)rg * ldc + cg] =
                        pack2(__float2half_rn(c0), __float2half_rn(c1));
                }
            }
        }
    }
}

// ============================ fused flash attention ============================
// q-tile 64 rows, 128 threads (4 warps x 16 q-rows), 2-stage KV, 2 CTAs/SM.
__global__ void __launch_bounds__(128, 2)
fattn_kernel(const f16* __restrict__ qkvhi, const f16* __restrict__ qkvlo,
             const float* __restrict__ x, float* __restrict__ attn) {
    constexpr int BUF  = 128 * 128;       // KV tile buffer: 128 rows x 128B
    constexpr int QBUF = 64 * 128;        // Q tile buffer: 64 rows x 128B
    constexpr int LD   = 3 * EMB;
    constexpr int NJT  = SEQ / 128;       // 16 kv tiles
    extern __shared__ char smem[];
    uint32_t sb = smem_u32(smem);
    const uint32_t QHb = sb, QLb = sb + QBUF;
    const uint32_t ST0 = sb + 2 * QBUF;   // + s*3*BUF : KH,KL,VH (s in 0..1)

    int tid = threadIdx.x, wid = tid >> 5, lane = tid & 31;
    int sub = lane >> 3, r = lane & 7;
    int z = blockIdx.y, zb = z >> 4, zh = z & 15;
    int m0 = blockIdx.x * 64;

    const size_t rowbase = (size_t)zb * SEQ;
    const int qcol = zh * DH, kcol = EMB + zh * DH, vcol = 2 * EMB + zh * DH;

    // Q tile load: 64 rows x 8 segs x 2 planes = 1024 chunks / 128 thr = 8 iters
#pragma unroll
    for (int t = 0; t < 4; t++) {
        int idx = tid + t * 128;
        int row = idx >> 3, seg = idx & 7;
        size_t go = (rowbase + m0 + row) * LD + qcol + seg * 8;
        uint32_t so = SWZ(row * 128 + seg * 16);
        cpasync16(QHb + so, qkvhi + go);
        cpasync16(QLb + so, qkvlo + go);
    }
    CP_COMMIT();
    auto load_kv = [&](int j, int s) {
        uint32_t base = ST0 + s * 3 * BUF;
        int k0 = j * 128;
#pragma unroll
        for (int t = 0; t < 8; t++) {
            int idx = tid + t * 128;
            int row = idx >> 3, seg = idx & 7;
            size_t gk = (rowbase + k0 + row) * LD + kcol + seg * 8;
            size_t gv = (rowbase + k0 + row) * LD + vcol + seg * 8;
            uint32_t so = SWZ(row * 128 + seg * 16);
            cpasync16(base + 0 * BUF + so, qkvhi + gk);
            cpasync16(base + 1 * BUF + so, qkvlo + gk);
            cpasync16(base + 2 * BUF + so, qkvhi + gv);
        }
        CP_COMMIT();
    };
    load_kv(0, 0);

    uint32_t qh[4][4], ql[4][4];
    float mr0 = -1e30f, mr1 = -1e30f, lr0 = 0.f, lr1 = 0.f;
    float oacc[8][4];
#pragma unroll
    for (int d = 0; d < 8; d++)
#pragma unroll
        for (int t = 0; t < 4; t++) oacc[d][t] = 0.f;

    for (int j = 0; j < NJT; j++) {
        int s = j & 1;
        CP_WAIT0();
        __syncthreads();
        if (j == 0) {
#pragma unroll
            for (int ks = 0; ks < 4; ks++) {
                int row = wid * 16 + (sub & 1) * 8 + r;
                int kb  = ks * 32 + (sub >> 1) * 16;
                uint32_t so = SWZ(row * 128 + kb);
                ldm_x4(qh[ks], QHb + so);
                ldm_x4(ql[ks], QLb + so);
            }
        }
        if (j + 1 < NJT) load_kv(j + 1, s ^ 1);

        uint32_t KHb = ST0 + s * 3 * BUF;
        uint32_t KLb = KHb + BUF, VHb = KLb + BUF;

        // ---- S = Q K^T (split 3-MMA) ----
        float sacc[16][4];
#pragma unroll
        for (int g = 0; g < 16; g++)
#pragma unroll
            for (int t = 0; t < 4; t++) sacc[g][t] = 0.f;

#pragma unroll
        for (int ks = 0; ks < 4; ks++) {
#pragma unroll
            for (int g = 0; g < 8; g++) {
                uint32_t bh[4], bl[4];
                int nrow = g * 16 + (sub >> 1) * 8 + r;
                int kb   = ks * 32 + (sub & 1) * 16;
                uint32_t so = SWZ(nrow * 128 + kb);
                ldm_x4(bh, KHb + so);
                ldm_x4(bl, KLb + so);
#pragma unroll
                for (int s2 = 0; s2 < 2; s2++) {
                    float* c = sacc[g * 2 + s2];
                    mma16816(c, qh[ks], &bh[s2 * 2]);
                    mma16816(c, qh[ks], &bl[s2 * 2]);
                    mma16816(c, ql[ks], &bh[s2 * 2]);
                }
            }
        }

        // ---- row max + oacc rescale ----
        float mx0 = -1e30f, mx1 = -1e30f;
#pragma unroll
        for (int g = 0; g < 16; g++) {
            mx0 = fmaxf(mx0, fmaxf(sacc[g][0], sacc[g][1]));
            mx1 = fmaxf(mx1, fmaxf(sacc[g][2], sacc[g][3]));
        }
        mx0 = fmaxf(mx0, __shfl_xor_sync(0xFFFFFFFFu, mx0, 1));
        mx0 = fmaxf(mx0, __shfl_xor_sync(0xFFFFFFFFu, mx0, 2));
        mx1 = fmaxf(mx1, __shfl_xor_sync(0xFFFFFFFFu, mx1, 1));
        mx1 = fmaxf(mx1, __shfl_xor_sync(0xFFFFFFFFu, mx1, 2));

        float mn0 = fmaxf(mr0, mx0), mn1 = fmaxf(mr1, mx1);
        float a0 = __expf(mr0 - mn0), a1 = __expf(mr1 - mn1);
        mr0 = mn0; mr1 = mn1;
#pragma unroll
        for (int d = 0; d < 8; d++) {
            oacc[d][0] *= a0; oacc[d][1] *= a0;
            oacc[d][2] *= a1; oacc[d][3] *= a1;
        }
        lr0 *= a0; lr1 *= a1;

        // ---- interleaved exp + PV (P hi x V: 1 MMA) ----
        float sum0 = 0.f, sum1 = 0.f;
#pragma unroll
        for (int t = 0; t < 8; t++) {
            float e00 = __expf(sacc[2 * t][0] - mn0);
            float e01 = __expf(sacc[2 * t][1] - mn0);
            float e02 = __expf(sacc[2 * t][2] - mn1);
            float e03 = __expf(sacc[2 * t][3] - mn1);
            float e10 = __expf(sacc[2 * t + 1][0] - mn0);
            float e11 = __expf(sacc[2 * t + 1][1] - mn0);
            float e12 = __expf(sacc[2 * t + 1][2] - mn1);
            float e13 = __expf(sacc[2 * t + 1][3] - mn1);
            sum0 += (e00 + e01) + (e10 + e11);
            sum1 += (e02 + e03) + (e12 + e13);

            uint32_t pah[4];
            pah[0] = pack2(__float2half_rn(e00), __float2half_rn(e01));
            pah[1] = pack2(__float2half_rn(e02), __float2half_rn(e03));
            pah[2] = pack2(__float2half_rn(e10), __float2half_rn(e11));
            pah[3] = pack2(__float2half_rn(e12), __float2half_rn(e13));
#pragma unroll
            for (int gd = 0; gd < 4; gd++) {
                uint32_t vh4[4];
                int krow = t * 16 + (sub & 1) * 8 + r;
                int nb   = gd * 32 + (sub >> 1) * 16;
                ldm_x4_t(vh4, VHb + SWZ(krow * 128 + nb));
#pragma unroll
                for (int s2 = 0; s2 < 2; s2++)
                    mma16816(oacc[gd * 2 + s2], pah, &vh4[s2 * 2]);
            }
        }
        sum0 += __shfl_xor_sync(0xFFFFFFFFu, sum0, 1);
        sum0 += __shfl_xor_sync(0xFFFFFFFFu, sum0, 2);
        sum1 += __shfl_xor_sync(0xFFFFFFFFu, sum1, 1);
        sum1 += __shfl_xor_sync(0xFFFFFFFFu, sum1, 2);
        lr0 += sum0;
        lr1 += sum1;
    }

    float li0 = 1.f / lr0, li1 = 1.f / lr1;
    int qr = lane >> 2, qc = (lane & 3) * 2;
    size_t row0 = rowbase + m0 + wid * 16 + qr;
    size_t row1 = row0 + 8;
#pragma unroll
    for (int gd = 0; gd < 8; gd++) {
        int cg = zh * DH + gd * 8 + qc;
        float2 xr0 = *(const float2*)&x[row0 * EMB + cg];
        float2 xr1 = *(const float2*)&x[row1 * EMB + cg];
        float2 o0 = make_float2(oacc[gd][0] * li0 + xr0.x, oacc[gd][1] * li0 + xr0.y);
        float2 o1 = make_float2(oacc[gd][2] * li1 + xr1.x, oacc[gd][3] * li1 + xr1.y);
        *(float2*)&attn[row0 * EMB + cg] = o0;
        *(float2*)&attn[row1 * EMB + cg] = o1;
    }
}

// ============================ LayerNorm + (optional) split ============================
__global__ void ln_split_kernel(const float* __restrict__ x,
                                const float* __restrict__ gamma,
                                const float* __restrict__ beta,
                                f16* __restrict__ ohi, f16* __restrict__ olo) {
    int row = blockIdx.x;
    const float* xr = x + (size_t)row * EMB;
    int tid = threadIdx.x;
    float v[4];
    float s = 0.f, s2 = 0.f;
#pragma unroll
    for (int i = 0; i < 4; i++) {
        float t = xr[tid + i * 256];
        v[i] = t; s += t; s2 += t * t;
    }
#pragma unroll
    for (int o = 16; o > 0; o >>= 1) {
        s  += __shfl_down_sync(0xFFFFFFFFu, s,  o);
        s2 += __shfl_down_sync(0xFFFFFFFFu, s2, o);
    }
    __shared__ float rs[8], rs2[8], mu_s, rstd_s;
    int wid = tid >> 5, lane = tid & 31;
    if (lane == 0) { rs[wid] = s; rs2[wid] = s2; }
    __syncthreads();
    if (wid == 0) {
        float a  = (lane < 8) ? rs[lane]  : 0.f;
        float a2 = (lane < 8) ? rs2[lane] : 0.f;
#pragma unroll
        for (int o = 4; o > 0; o >>= 1) {
            a  += __shfl_down_sync(0xFFFFFFFFu, a,  o);
            a2 += __shfl_down_sync(0xFFFFFFFFu, a2, o);
        }
        if (lane == 0) {
            float mu = a * (1.0f / EMB);
            mu_s = mu;
            rstd_s = rsqrtf(a2 * (1.0f / EMB) - mu * mu + 1e-6f);
        }
    }
    __syncthreads();
    float mu = mu_s, rstd = rstd_s;
#pragma unroll
    for (int i = 0; i < 4; i++) {
        int c = tid + i * 256;
        float val = (v[i] - mu) * rstd * gamma[c] + beta[c];
        f16 h_, l_; split2(val, h_, l_);
        ohi[(size_t)row * EMB + c] = h_;
        if (olo) olo[(size_t)row * EMB + c] = l_;
    }
}

// ============================ combined weight prep ============================
__global__ void prep_kernel(const float* __restrict__ Wq, const float* __restrict__ Wk,
                            const float* __restrict__ Wv, const float* __restrict__ W1,
                            const float* __restrict__ W2,
                            const float* __restrict__ bq, const float* __restrict__ bk,
                            const float* __restrict__ bv,
                            f16* __restrict__ wqkvhi, f16* __restrict__ wqkvlo,
                            f16* __restrict__ w1hi, f16* __restrict__ w2hi,
                            float* __restrict__ bqkv) {
    int bid = blockIdx.x;
    int tx = threadIdx.x, ty = threadIdx.y;
    int tid = ty * 32 + tx;

    if (bid == 0) {
        for (int i = tid; i < EMB; i += 256) {
            bqkv[i]           = bq[i];
            bqkv[EMB + i]     = bk[i];
            bqkv[2 * EMB + i] = bv[i];
        }
    }

    const float* W; f16 *Thi, *Tlo; int K, N, nx, ky;
    if (bid < 3072) {
        int w = bid >> 10, t = bid & 1023;
        W = (w == 0) ? Wq : (w == 1) ? Wk : Wv;
        Thi = wqkvhi + (size_t)w * EMB * EMB;
        Tlo = wqkvlo + (size_t)w * EMB * EMB;
        K = EMB; N = EMB; nx = t & 31; ky = t >> 5;
    } else if (bid < 7168) {
        int t = bid - 3072;
        W = W1; Thi = w1hi; Tlo = nullptr;
        K = EMB; N = DFF; nx = t & 127; ky = t >> 7;
    } else {
        int t = bid - 7168;
        W = W2; Thi = w2hi; Tlo = nullptr;
        K = DFF; N = EMB; nx = t & 31; ky = t >> 5;
    }
    int n0 = nx * 32, k0 = ky * 32;

    __shared__ float tbuf[32][33];
#pragma unroll
    for (int i = ty; i < 32; i += 8)
        tbuf[i][tx] = W[(size_t)(k0 + i) * N + n0 + tx];
    __syncthreads();
#pragma unroll
    for (int i = ty; i < 32; i += 8) {
        float v = tbuf[tx][i];
        f16 h_, l_; split2(v, h_, l_);
        size_t oi = (size_t)(n0 + i) * K + k0 + tx;
        Thi[oi] = h_;
        if (Tlo) Tlo[oi] = l_;
    }
}

// ============================ launch ============================
extern "C" void kernel_launch(void* const* d_in, const int* in_sizes, int n_in,
                              void* d_out, int out_size) {
    const float* x   = (const float*)d_in[0];
    const float* Wq  = (const float*)d_in[1];
    const float* bq  = (const float*)d_in[2];
    const float* Wk  = (const float*)d_in[3];
    const float* bk  = (const float*)d_in[4];
    const float* Wv  = (const float*)d_in[5];
    const float* bv  = (const float*)d_in[6];
    const float* g1  = (const float*)d_in[7];
    const float* be1 = (const float*)d_in[8];
    const float* g2  = (const float*)d_in[9];
    const float* be2 = (const float*)d_in[10];
    const float* W1  = (const float*)d_in[11];
    const float* b1  = (const float*)d_in[12];
    const float* W2  = (const float*)d_in[13];
    const float* b2  = (const float*)d_in[14];
    float* out = (float*)d_out;

    f16 *hhi, *hlo, *wqkvhi, *wqkvlo, *w1hi, *w2hi;
    f16 *qkvhi, *qkvlo, *h2hi, *ffhi;
    float *attn, *bqkv;
    cudaGetSymbolAddress((void**)&hhi,    g_hhi);    cudaGetSymbolAddress((void**)&hlo,    g_hlo);
    cudaGetSymbolAddress((void**)&wqkvhi, g_wqkvhi); cudaGetSymbolAddress((void**)&wqkvlo, g_wqkvlo);
    cudaGetSymbolAddress((void**)&w1hi,   g_w1hi);
    cudaGetSymbolAddress((void**)&w2hi,   g_w2hi);
    cudaGetSymbolAddress((void**)&qkvhi,  g_qkvhi);  cudaGetSymbolAddress((void**)&qkvlo,  g_qkvlo);
    cudaGetSymbolAddress((void**)&attn,   g_attn);
    cudaGetSymbolAddress((void**)&h2hi,   g_h2hi);
    cudaGetSymbolAddress((void**)&ffhi,   g_ffhi);
    cudaGetSymbolAddress((void**)&bqkv,   g_bqkv);

    const int SMEM_G3 = 2 * (2 * 128 * 128 + 2 * 256 * 128);   // 196608
    const int SMEM_G1 = 3 * (128 * 128 + 128 * 128);            //  98304
    const int SMEM_F  = 2 * 64 * 128 + 2 * 3 * 128 * 128;      // 114688... (16K + 96K = 112K)
    cudaFuncSetAttribute(gemm3_kernel, cudaFuncAttributeMaxDynamicSharedMemorySize, SMEM_G3);
    cudaFuncSetAttribute(gemm1_kernel, cudaFuncAttributeMaxDynamicSharedMemorySize, SMEM_G1);
    cudaFuncSetAttribute(fattn_kernel, cudaFuncAttributeMaxDynamicSharedMemorySize, SMEM_F);

    // 0) weight prep
    prep_kernel<<<11264, dim3(32, 8)>>>(Wq, Wk, Wv, W1, W2, bq, bk, bv,
                                        wqkvhi, wqkvlo, w1hi, w2hi, bqkv);

    // 1) LN1 -> split
    ln_split_kernel<<<TOK, 256>>>(x, g1, be1, hhi, hlo);

    // 2a) q,k projection (3-MMA split) -> packed qkv cols [0,2048)
    {
        dim3 grid(2 * EMB / 256, TOK / 128);
        gemm3_kernel<<<grid, 256, SMEM_G3>>>(hhi, hlo, wqkvhi, wqkvlo, bqkv, qkvhi, qkvlo);
    }
    // 2b) v projection (1-MMA, hi-only A) -> packed qkv cols [2048,3072)
    {
        dim3 grid(EMB / 128, TOK / 128);
        gemm1_kernel<<<grid, 256, SMEM_G1>>>(
            hhi, EMB, wqkvhi + (size_t)2 * EMB * EMB, EMB,
            bqkv + 2 * EMB, nullptr, 0,
            qkvhi + 2 * EMB, 3 * EMB, EMB, 1);
    }

    // 3) fused attention (+ residual x) -> attn   [64-row q tiles, 2 CTAs/SM]
    {
        dim3 grid(SEQ / 64, BATCH * HEADS);
        fattn_kernel<<<grid, 128, SMEM_F>>>(qkvhi, qkvlo, x, attn);
    }

    // 4) LN2 -> single f16
    ln_split_kernel<<<TOK, 256>>>(attn, g2, be2, h2hi, nullptr);

    // 5) FFN1 (1-MMA, bias+gelu) -> f16
    {
        dim3 grid(DFF / 128, TOK / 128);
        gemm1_kernel<<<grid, 256, SMEM_G1>>>(h2hi, EMB, w1hi, EMB,
                                             b1, nullptr, 0, ffhi, DFF, EMB, 3);
    }

    // 6) FFN2 (1-MMA, bias + attn residual) -> d_out
    {
        dim3 grid(EMB / 128, TOK / 128);
        gemm1_kernel<<<grid, 256, SMEM_G1>>>(ffhi, DFF, w2hi, DFF,
                                             b2, attn, EMB, out, EMB, DFF, 4);
    }
}